// round 10
// baseline (speedup 1.0000x reference)
#include <cuda_runtime.h>
#include <math.h>
#include <cstdint>

#define B_ 4
#define T_ 2048
#define E_ 1024
#define BT_ (B_*T_)
#define SEG_ 16
#define SEGL_ (T_/SEG_)   // 128

// ---------------- scratch (device globals; no allocation allowed) ----------
__device__ float g_ctx[BT_*E_];
__device__ float g_gated[BT_*E_];
__device__ float g_temporal[BT_*E_];
__device__ float g_gate[BT_*E_];
__device__ float g_sg[BT_*E_];
__device__ float g_h1[BT_*256];
__device__ float g_mod[BT_*4];
__device__ float g_seg[B_*SEG_*E_];
__device__ float g_seg4[4*B_*SEG_*E_];
__device__ float g_xr[BT_*E_];
__device__ float g_wgr[E_*2*E_];
__device__ float g_wn1r[256*E_];
__device__ float g_wtr[E_*E_];
__device__ float g_wsr[E_*E_];
__device__ float g_wor[E_*E_];

// ---------------- helpers --------------------------------------------------
__device__ __forceinline__ float sigmoidf_(float x) { return 1.0f / (1.0f + expf(-x)); }
__device__ __forceinline__ float geluf_(float x) {
    return 0.5f * x * (1.0f + erff(x * 0.70710678118654752440f));
}
__device__ __forceinline__ uint32_t to_tf32(float x) {
    uint32_t r;
    asm("cvt.rna.tf32.f32 %0, %1;" : "=r"(r) : "f"(x));
    return r;
}
__device__ __forceinline__ float tf32f(float x) { return __uint_as_float(to_tf32(x)); }

__device__ __forceinline__ uint32_t smem_u32(const void* p) {
    uint32_t a;
    asm("{ .reg .u64 t; cvta.to.shared.u64 t, %1; cvt.u32.u64 %0, t; }" : "=r"(a) : "l"(p));
    return a;
}

#define LDSM_X4(d, addr) \
    asm volatile("ldmatrix.sync.aligned.m8n8.x4.shared.b16 {%0,%1,%2,%3}, [%4];" \
                 : "=r"((d)[0]), "=r"((d)[1]), "=r"((d)[2]), "=r"((d)[3]) : "r"(addr))

#define CP_ASYNC16(dst, src) \
    asm volatile("cp.async.cg.shared.global [%0], [%1], 16;" :: "r"(dst), "l"(src))

// ============================================================================
// Launch 1: ema_ctx_p1 fused with round_x (reads x once; writes xr + seg)
// ============================================================================
__global__ void ema_ctx_p1_roundx(const float* __restrict__ x,
                                  const float* __restrict__ tau_ctx,
                                  float* __restrict__ seg,
                                  float* __restrict__ xr) {
    int tid = blockIdx.x * blockDim.x + threadIdx.x;    // B*E*SEG threads
    if (tid >= B_ * E_ * SEG_) return;
    int e = tid & (E_ - 1);
    int s = (tid >> 10) & (SEG_ - 1);
    int b = tid >> 14;
    float alpha = 1.0f / (1.0f + expf(tau_ctx[0]));
    size_t base = ((size_t)(b * T_ + s * SEGL_)) * E_ + e;
    float h = 0.0f;
    for (int t = 0; t < SEGL_; t += 8) {
        float v[8];
#pragma unroll
        for (int i = 0; i < 8; i++) v[i] = __ldg(&x[base + (size_t)(t + i) * E_]);
#pragma unroll
        for (int i = 0; i < 8; i++) {
            h = fmaf(alpha, h, v[i]);
            xr[base + (size_t)(t + i) * E_] = tf32f(v[i]);
        }
    }
    seg[(b * SEG_ + s) * E_ + e] = h;
}

// ============================================================================
// Launch 2: ema_ctx_p2 (carry scan, 4096 threads) fused with round_w
// (all other threads round the 5 weight matrices grid-stride)
// ============================================================================
__global__ void ema_ctx_p2_roundw(const float* __restrict__ tau_ctx,
                                  float* __restrict__ seg,
                                  const float* __restrict__ Wg,  const float* __restrict__ Wn1,
                                  const float* __restrict__ Wt,  const float* __restrict__ Ws,
                                  const float* __restrict__ Wo,
                                  float* __restrict__ wgr, float* __restrict__ wn1r,
                                  float* __restrict__ wtr, float* __restrict__ wsr,
                                  float* __restrict__ wor) {
    int tid = blockIdx.x * blockDim.x + threadIdx.x;
    // --- part 1: carry scan for the first B_*E_ threads ---
    if (tid < B_ * E_) {
        int e = tid & (E_ - 1);
        int b = tid >> 10;
        float alpha = 1.0f / (1.0f + expf(tau_ctx[0]));
        float aL = 1.0f;
        for (int k = 0; k < SEGL_; k++) aL *= alpha;
        float carry = 0.0f;
        for (int s = 0; s < SEG_; s++) {
            size_t idx = (size_t)(b * SEG_ + s) * E_ + e;
            float Es = seg[idx];
            seg[idx] = carry;
            carry = fmaf(aL, carry, Es);
        }
    }
    // --- part 2: weight rounding, all threads grid-stride ---
    const int n_wg  = E_ * 2 * E_ / 4;
    const int n_wn1 = 256 * E_ / 4;
    const int n_w   = E_ * E_ / 4;
    const int total = n_wg + n_wn1 + 3 * n_w;
    int stride = gridDim.x * blockDim.x;
    for (int i = tid; i < total; i += stride) {
        const float* src; float* dst; int j = i;
        if (j < n_wg) { src = Wg; dst = wgr; }
        else {
            j -= n_wg;
            if (j < n_wn1) { src = Wn1; dst = wn1r; }
            else {
                j -= n_wn1;
                int k = j / n_w; j -= k * n_w;
                src = (k == 0) ? Wt : (k == 1) ? Ws : Wo;
                dst = (k == 0) ? wtr : (k == 1) ? wsr : wor;
            }
        }
        float4 v = reinterpret_cast<const float4*>(src)[j];
        v.x = tf32f(v.x); v.y = tf32f(v.y); v.z = tf32f(v.z); v.w = tf32f(v.w);
        reinterpret_cast<float4*>(dst)[j] = v;
    }
}

// ============================================================================
// Launch 3: ema_ctx_p3 — replay with carry, store tf32-rounded ctx
// ============================================================================
__global__ void ema_ctx_p3(const float* __restrict__ x,
                           const float* __restrict__ tau_ctx,
                           const float* __restrict__ seg,
                           float* __restrict__ ctx) {
    int tid = blockIdx.x * blockDim.x + threadIdx.x;
    if (tid >= B_ * E_ * SEG_) return;
    int e = tid & (E_ - 1);
    int s = (tid >> 10) & (SEG_ - 1);
    int b = tid >> 14;
    float alpha = 1.0f / (1.0f + expf(tau_ctx[0]));
    size_t base = ((size_t)(b * T_ + s * SEGL_)) * E_ + e;
    float h = seg[(b * SEG_ + s) * E_ + e];
    for (int t = 0; t < SEGL_; t += 8) {
        float v[8];
#pragma unroll
        for (int i = 0; i < 8; i++) v[i] = __ldg(&x[base + (size_t)(t + i) * E_]);
#pragma unroll
        for (int i = 0; i < 8; i++) {
            h = fmaf(alpha, h, v[i]);
            ctx[base + (size_t)(t + i) * E_] = tf32f(h);
        }
    }
}

// ============================================================================
// Segmented EMA for the 4 modulated traces + softmax blend
// ============================================================================
__global__ void ema_tr_p1(const float* __restrict__ gated,
                          const float* __restrict__ mod,
                          const float* __restrict__ tau_raws,
                          float* __restrict__ seg4) {
    int tid = blockIdx.x * blockDim.x + threadIdx.x;
    if (tid >= B_ * E_ * SEG_) return;
    int e = tid & (E_ - 1);
    int s = (tid >> 10) & (SEG_ - 1);
    int b = tid >> 14;
    float al[4];
#pragma unroll
    for (int d = 0; d < 4; d++) al[d] = 1.0f / (1.0f + expf(tau_raws[d]));
    size_t base = ((size_t)(b * T_ + s * SEGL_)) * E_ + e;
    const float4* mod4 = reinterpret_cast<const float4*>(mod);
    size_t mbase = (size_t)b * T_ + s * SEGL_;
    float h0 = 0.f, h1 = 0.f, h2 = 0.f, h3 = 0.f;
    for (int t = 0; t < SEGL_; t += 4) {
        float g[4]; float4 mm[4];
#pragma unroll
        for (int i = 0; i < 4; i++) {
            g[i]  = __ldg(&gated[base + (size_t)(t + i) * E_]);
            mm[i] = __ldg(&mod4[mbase + t + i]);
        }
#pragma unroll
        for (int i = 0; i < 4; i++) {
            h0 = fmaf(al[0], h0, g[i] * mm[i].x);
            h1 = fmaf(al[1], h1, g[i] * mm[i].y);
            h2 = fmaf(al[2], h2, g[i] * mm[i].z);
            h3 = fmaf(al[3], h3, g[i] * mm[i].w);
        }
    }
    size_t o = (size_t)(b * SEG_ + s) * E_ + e;
    seg4[0 * (B_*SEG_*E_) + o] = h0;
    seg4[1 * (B_*SEG_*E_) + o] = h1;
    seg4[2 * (B_*SEG_*E_) + o] = h2;
    seg4[3 * (B_*SEG_*E_) + o] = h3;
}

__global__ void ema_tr_p2(const float* __restrict__ tau_raws,
                          float* __restrict__ seg4) {
    int tid = blockIdx.x * blockDim.x + threadIdx.x;
    if (tid >= B_ * E_) return;
    int e = tid & (E_ - 1);
    int b = tid >> 10;
#pragma unroll
    for (int d = 0; d < 4; d++) {
        float alpha = 1.0f / (1.0f + expf(tau_raws[d]));
        float aL = 1.0f;
        for (int k = 0; k < SEGL_; k++) aL *= alpha;
        float carry = 0.0f;
        for (int s = 0; s < SEG_; s++) {
            size_t idx = (size_t)d * (B_*SEG_*E_) + (size_t)(b * SEG_ + s) * E_ + e;
            float Es = seg4[idx];
            seg4[idx] = carry;
            carry = fmaf(aL, carry, Es);
        }
    }
}

// temporal only feeds the Wtemp GEMM -> store tf32-rounded
__global__ void ema_tr_p3(const float* __restrict__ gated,
                          const float* __restrict__ mod,
                          const float* __restrict__ tau_raws,
                          const float* __restrict__ blend,
                          const float* __restrict__ seg4,
                          float* __restrict__ temporal) {
    int tid = blockIdx.x * blockDim.x + threadIdx.x;
    if (tid >= B_ * E_ * SEG_) return;
    int e = tid & (E_ - 1);
    int s = (tid >> 10) & (SEG_ - 1);
    int b = tid >> 14;

    float al[4];
#pragma unroll
    for (int d = 0; d < 4; d++) al[d] = 1.0f / (1.0f + expf(tau_raws[d]));

    float bl[4];
#pragma unroll
    for (int d = 0; d < 4; d++) bl[d] = blend[d * E_ + e];
    float mx = fmaxf(fmaxf(bl[0], bl[1]), fmaxf(bl[2], bl[3]));
    float bw[4], sum = 0.0f;
#pragma unroll
    for (int d = 0; d < 4; d++) { bw[d] = expf(bl[d] - mx); sum += bw[d]; }
    float inv = 1.0f / sum;
#pragma unroll
    for (int d = 0; d < 4; d++) bw[d] *= inv;

    size_t base = ((size_t)(b * T_ + s * SEGL_)) * E_ + e;
    const float4* mod4 = reinterpret_cast<const float4*>(mod);
    size_t mbase = (size_t)b * T_ + s * SEGL_;
    size_t o = (size_t)(b * SEG_ + s) * E_ + e;
    float h0 = seg4[0 * (B_*SEG_*E_) + o];
    float h1 = seg4[1 * (B_*SEG_*E_) + o];
    float h2 = seg4[2 * (B_*SEG_*E_) + o];
    float h3 = seg4[3 * (B_*SEG_*E_) + o];

    for (int t = 0; t < SEGL_; t += 4) {
        float g[4]; float4 mm[4];
#pragma unroll
        for (int i = 0; i < 4; i++) {
            g[i]  = __ldg(&gated[base + (size_t)(t + i) * E_]);
            mm[i] = __ldg(&mod4[mbase + t + i]);
        }
#pragma unroll
        for (int i = 0; i < 4; i++) {
            h0 = fmaf(al[0], h0, g[i] * mm[i].x);
            h1 = fmaf(al[1], h1, g[i] * mm[i].y);
            h2 = fmaf(al[2], h2, g[i] * mm[i].z);
            h3 = fmaf(al[3], h3, g[i] * mm[i].w);
            temporal[base + (size_t)(t + i) * E_] =
                tf32f(bw[0] * h0 + bw[1] * h1 + bw[2] * h2 + bw[3] * h3);
        }
    }
}

// ============================================================================
// tf32 mma.sync GEMM, cp.async 3-stage pipeline + swizzled k-major + ldmatrix
// (unchanged from R8/R9 — the proven kernel)
// mode: 0 none, 1 sigmoid(.)*extra, 2 gelu, 3 sigmoid, 4 gelu(.)*extra+round
// ============================================================================
static constexpr int STAGE_BYTES = 32768;    // A 16KB + B 16KB
static constexpr int NSTAGE = 3;
static constexpr int LDC = 132;
static constexpr int DYN_SMEM = NSTAGE * STAGE_BYTES;  // 98304

__global__ void __launch_bounds__(256, 2)
gemm_mma(const float* __restrict__ A, const float* __restrict__ A2, int KA,
         const float* __restrict__ W, const float* __restrict__ bias,
         const float* __restrict__ extra, float* __restrict__ C,
         int N, int K, int mode) {
    extern __shared__ float smem[];
    uint32_t sb = smem_u32(smem);
    int tid = threadIdx.x, wid = tid >> 5, lane = tid & 31;
    int bm = blockIdx.y * 128, bn = blockIdx.x * 128;
    int wm = wid & 1;
    int wn = wid >> 1;

    float acc[4][4][4];
#pragma unroll
    for (int i = 0; i < 4; i++)
#pragma unroll
        for (int j = 0; j < 4; j++)
#pragma unroll
            for (int r = 0; r < 4; r++) acc[i][j][r] = 0.0f;

    const int NC = K / 32;

    int p7 = lane & 7;
    uint32_t aRow[4], bRow[2];
#pragma unroll
    for (int i = 0; i < 4; i++)
        aRow[i] = (uint32_t)(wm * 64 + i * 16 + p7 + 8 * ((lane >> 3) & 1)) * 128u;
#pragma unroll
    for (int j2 = 0; j2 < 2; j2++)
        bRow[j2] = (uint32_t)(wn * 32 + j2 * 16 + p7 + 8 * (lane >> 4)) * 128u;
    uint32_t swzA[4], swzB[4];
#pragma unroll
    for (int ks = 0; ks < 4; ks++) {
        swzA[ks] = (uint32_t)(((ks * 2 + (lane >> 4)) ^ p7) * 16);
        swzB[ks] = (uint32_t)(((ks * 2 + ((lane >> 3) & 1)) ^ p7) * 16);
    }

    auto load_chunk = [&](int c, int s) {
        int k0 = c * 32;
        const float* srcA = A; int ka = k0;
        if (A2 != nullptr && k0 >= KA) { srcA = A2; ka = k0 - KA; }
        uint32_t dstA = sb + (uint32_t)s * STAGE_BYTES;
        uint32_t dstB = dstA + 16384;
#pragma unroll
        for (int q = 0; q < 4; q++) {
            int idx = tid + q * 256;
            int row = idx >> 3, ch = idx & 7;
            uint32_t off = (uint32_t)row * 128u + (uint32_t)((ch ^ (row & 7)) * 16);
            const float* sA = srcA + (size_t)(bm + row) * KA + ka + ch * 4;
            CP_ASYNC16(dstA + off, sA);
            const float* sB = W + (size_t)(bn + row) * K + k0 + ch * 4;
            CP_ASYNC16(dstB + off, sB);
        }
        asm volatile("cp.async.commit_group;" ::: "memory");
    };

    load_chunk(0, 0);
    load_chunk(1, 1);

    for (int c = 0; c < NC; c++) {
        int s = c % NSTAGE;
        if (c < NC - 1) asm volatile("cp.async.wait_group 1;" ::: "memory");
        else            asm volatile("cp.async.wait_group 0;" ::: "memory");
        __syncthreads();
        if (c + 2 < NC) load_chunk(c + 2, (c + 2) % NSTAGE);

        uint32_t baseA = sb + (uint32_t)s * STAGE_BYTES;
        uint32_t baseB = baseA + 16384;
#pragma unroll
        for (int ks = 0; ks < 4; ks++) {
            uint32_t a[4][4], b[2][4];
#pragma unroll
            for (int i = 0; i < 4; i++) LDSM_X4(a[i], baseA + aRow[i] + swzA[ks]);
#pragma unroll
            for (int j2 = 0; j2 < 2; j2++) LDSM_X4(b[j2], baseB + bRow[j2] + swzB[ks]);
#pragma unroll
            for (int i = 0; i < 4; i++)
#pragma unroll
                for (int j = 0; j < 4; j++) {
                    asm volatile(
                        "mma.sync.aligned.m16n8k8.row.col.f32.tf32.tf32.f32 "
                        "{%0,%1,%2,%3}, {%4,%5,%6,%7}, {%8,%9}, {%0,%1,%2,%3};"
                        : "+f"(acc[i][j][0]), "+f"(acc[i][j][1]),
                          "+f"(acc[i][j][2]), "+f"(acc[i][j][3])
                        : "r"(a[i][0]), "r"(a[i][1]), "r"(a[i][2]), "r"(a[i][3]),
                          "r"(b[j >> 1][(j & 1) * 2]), "r"(b[j >> 1][(j & 1) * 2 + 1]));
                }
        }
    }
    __syncthreads();

    // -------- epilogue ----------------------------------------------------
    float* Cs = smem;
#pragma unroll
    for (int i = 0; i < 4; i++)
#pragma unroll
        for (int j = 0; j < 4; j++) {
            int r0 = wm * 64 + i * 16 + (lane >> 2);
            int c0 = wn * 32 + j * 8 + (lane & 3) * 2;
            *reinterpret_cast<float2*>(Cs + r0 * LDC + c0) =
                make_float2(acc[i][j][0], acc[i][j][1]);
            *reinterpret_cast<float2*>(Cs + (r0 + 8) * LDC + c0) =
                make_float2(acc[i][j][2], acc[i][j][3]);
        }
    __syncthreads();

    for (int t = tid; t < 128 * 32; t += 256) {
        int r = t >> 5, c0 = (t & 31) * 4;
        const float* rg = Cs + r * LDC + c0;
        int m = bm + r, n = bn + c0;
        size_t oidx = (size_t)m * N + n;
        float v[4];
#pragma unroll
        for (int i = 0; i < 4; i++) {
            v[i] = rg[i];
            if (bias != nullptr) v[i] += __ldg(&bias[n + i]);
        }
        if (mode == 1 || mode == 4) {
            float4 ex = *reinterpret_cast<const float4*>(extra + oidx);
            float exv[4] = {ex.x, ex.y, ex.z, ex.w};
#pragma unroll
            for (int i = 0; i < 4; i++)
                v[i] = (mode == 1) ? sigmoidf_(v[i]) * exv[i]
                                   : tf32f(geluf_(v[i]) * exv[i]);
        } else if (mode == 2) {
#pragma unroll
            for (int i = 0; i < 4; i++) v[i] = geluf_(v[i]);
        } else if (mode == 3) {
#pragma unroll
            for (int i = 0; i < 4; i++) v[i] = sigmoidf_(v[i]);
        }
        *reinterpret_cast<float4*>(C + oidx) = make_float4(v[0], v[1], v[2], v[3]);
    }
}

// ---------------- mod = 0.5 + sigmoid(h1 @ Wn2^T + bn2) ---------------------
__global__ void mod_kernel(const float* __restrict__ h1,
                           const float* __restrict__ Wn2,
                           const float* __restrict__ bn2,
                           float* __restrict__ mod) {
    int warp = (blockIdx.x * blockDim.x + threadIdx.x) >> 5;
    int lane = threadIdx.x & 31;
    if (warp >= BT_) return;
    const float* hr = h1 + (size_t)warp * 256;
    float a0 = 0.f, a1 = 0.f, a2 = 0.f, a3 = 0.f;
    for (int k = lane; k < 256; k += 32) {
        float hv = __ldg(&hr[k]);
        a0 = fmaf(hv, __ldg(&Wn2[k]),       a0);
        a1 = fmaf(hv, __ldg(&Wn2[256 + k]), a1);
        a2 = fmaf(hv, __ldg(&Wn2[512 + k]), a2);
        a3 = fmaf(hv, __ldg(&Wn2[768 + k]), a3);
    }
#pragma unroll
    for (int o = 16; o > 0; o >>= 1) {
        a0 += __shfl_xor_sync(0xffffffff, a0, o);
        a1 += __shfl_xor_sync(0xffffffff, a1, o);
        a2 += __shfl_xor_sync(0xffffffff, a2, o);
        a3 += __shfl_xor_sync(0xffffffff, a3, o);
    }
    if (lane == 0) {
        mod[(size_t)warp * 4 + 0] = 0.5f + sigmoidf_(a0 + bn2[0]);
        mod[(size_t)warp * 4 + 1] = 0.5f + sigmoidf_(a1 + bn2[1]);
        mod[(size_t)warp * 4 + 2] = 0.5f + sigmoidf_(a2 + bn2[2]);
        mod[(size_t)warp * 4 + 3] = 0.5f + sigmoidf_(a3 + bn2[3]);
    }
}

// ---------------- in-place LayerNorm over E per row --------------------------
__global__ void ln_kernel(float* __restrict__ out,
                          const float* __restrict__ gamma,
                          const float* __restrict__ beta) {
    int row = blockIdx.x;
    float* p = out + (size_t)row * E_;
    int tid = threadIdx.x;
    float v[4];
    float s = 0.f, ss = 0.f;
#pragma unroll
    for (int i = 0; i < 4; i++) {
        v[i] = p[tid + i * 256];
        s += v[i];
        ss += v[i] * v[i];
    }
#pragma unroll
    for (int o = 16; o > 0; o >>= 1) {
        s  += __shfl_down_sync(0xffffffff, s,  o);
        ss += __shfl_down_sync(0xffffffff, ss, o);
    }
    __shared__ float shs[8], shss[8];
    __shared__ float mu_s, inv_s;
    int wid = tid >> 5, lane = tid & 31;
    if (lane == 0) { shs[wid] = s; shss[wid] = ss; }
    __syncthreads();
    if (tid == 0) {
        float S = 0.f, SS = 0.f;
#pragma unroll
        for (int w = 0; w < 8; w++) { S += shs[w]; SS += shss[w]; }
        float mu  = S / (float)E_;
        float var = SS / (float)E_ - mu * mu;
        mu_s = mu;
        inv_s = rsqrtf(var + 1e-5f);
    }
    __syncthreads();
    float mu = mu_s, iv = inv_s;
#pragma unroll
    for (int i = 0; i < 4; i++) {
        int c = tid + i * 256;
        p[c] = (v[i] - mu) * iv * __ldg(&gamma[c]) + __ldg(&beta[c]);
    }
}

// ---------------- launch -----------------------------------------------------
extern "C" void kernel_launch(void* const* d_in, const int* in_sizes, int n_in,
                              void* d_out, int out_size) {
    const float* x        = (const float*)d_in[0];
    const float* tau_ctx  = (const float*)d_in[1];
    const float* tau_raws = (const float*)d_in[2];
    const float* Wg       = (const float*)d_in[3];
    const float* bg       = (const float*)d_in[4];
    const float* Wn1      = (const float*)d_in[5];
    const float* bn1      = (const float*)d_in[6];
    const float* Wn2      = (const float*)d_in[7];
    const float* bn2      = (const float*)d_in[8];
    const float* blend    = (const float*)d_in[9];
    const float* Wsoma    = (const float*)d_in[10];
    const float* bsoma    = (const float*)d_in[11];
    const float* Wtemp    = (const float*)d_in[12];
    const float* btemp    = (const float*)d_in[13];
    const float* Wout     = (const float*)d_in[14];
    const float* gamma    = (const float*)d_in[15];
    const float* beta     = (const float*)d_in[16];
    float* out = (float*)d_out;

    float *ctx, *gated, *temporal, *gate, *sg, *h1, *mod, *seg, *seg4;
    float *xr, *wgr, *wn1r, *wtr, *wsr, *wor;
    cudaGetSymbolAddress((void**)&ctx,      g_ctx);
    cudaGetSymbolAddress((void**)&gated,    g_gated);
    cudaGetSymbolAddress((void**)&temporal, g_temporal);
    cudaGetSymbolAddress((void**)&gate,     g_gate);
    cudaGetSymbolAddress((void**)&sg,       g_sg);
    cudaGetSymbolAddress((void**)&h1,       g_h1);
    cudaGetSymbolAddress((void**)&mod,      g_mod);
    cudaGetSymbolAddress((void**)&seg,      g_seg);
    cudaGetSymbolAddress((void**)&seg4,     g_seg4);
    cudaGetSymbolAddress((void**)&xr,       g_xr);
    cudaGetSymbolAddress((void**)&wgr,      g_wgr);
    cudaGetSymbolAddress((void**)&wn1r,     g_wn1r);
    cudaGetSymbolAddress((void**)&wtr,      g_wtr);
    cudaGetSymbolAddress((void**)&wsr,      g_wsr);
    cudaGetSymbolAddress((void**)&wor,      g_wor);

    cudaFuncSetAttribute(gemm_mma, cudaFuncAttributeMaxDynamicSharedMemorySize, DYN_SMEM);
    cudaFuncSetAttribute(gemm_mma, cudaFuncAttributePreferredSharedMemoryCarveout,
                         cudaSharedmemCarveoutMaxShared);

    const int NSEG_T = B_ * E_ * SEG_;

    // launch 1: ema_ctx p1 + round_x (reads x once)
    ema_ctx_p1_roundx<<<NSEG_T / 256, 256>>>(x, tau_ctx, seg, xr);
    // launch 2: ema_ctx p2 carry scan + round_w (all 5 weights)
    ema_ctx_p2_roundw<<<1024, 256>>>(tau_ctx, seg, Wg, Wn1, Wtemp, Wsoma, Wout,
                                     wgr, wn1r, wtr, wsr, wor);
    // launch 3: ema_ctx p3 -> ctx (tf32-rounded)
    ema_ctx_p3<<<NSEG_T / 256, 256>>>(x, tau_ctx, seg, ctx);

    // launch 4 (ncu captures this): gated = x * sigmoid([x,ctx]@Wg^T + bg)
    {
        dim3 grid(E_ / 128, BT_ / 128);
        gemm_mma<<<grid, 256, DYN_SMEM>>>(xr, ctx, E_, wgr, bg, x, gated, E_, 2 * E_, 1);
    }

    // h1 = gelu(x @ Wn1^T + bn1)
    {
        dim3 grid(256 / 128, BT_ / 128);
        gemm_mma<<<grid, 256, DYN_SMEM>>>(xr, nullptr, E_, wn1r, bn1, nullptr, h1, 256, E_, 2);
    }

    // mod = 0.5 + sigmoid(h1 @ Wn2^T + bn2)
    mod_kernel<<<(BT_ * 32) / 256, 256>>>(h1, Wn2, bn2, mod);

    // temporal — segmented 3-pass over 4 chains + blend
    ema_tr_p1<<<NSEG_T / 256, 256>>>(gated, mod, tau_raws, seg4);
    ema_tr_p2<<<(B_ * E_) / 256, 256>>>(tau_raws, seg4);
    ema_tr_p3<<<NSEG_T / 256, 256>>>(gated, mod, tau_raws, blend, seg4, temporal);

    // gate = sigmoid(temporal @ Wtemp^T + btemp)
    {
        dim3 grid(E_ / 128, BT_ / 128);
        gemm_mma<<<grid, 256, DYN_SMEM>>>(temporal, nullptr, E_, wtr, btemp, nullptr, gate, E_, E_, 3);
    }

    // sg = gelu(x @ Wsoma^T + bsoma) * gate
    {
        dim3 grid(E_ / 128, BT_ / 128);
        gemm_mma<<<grid, 256, DYN_SMEM>>>(xr, nullptr, E_, wsr, bsoma, gate, sg, E_, E_, 4);
    }

    // out = sg @ Wout^T
    {
        dim3 grid(E_ / 128, BT_ / 128);
        gemm_mma<<<grid, 256, DYN_SMEM>>>(sg, nullptr, E_, wor, nullptr, nullptr, out, E_, E_, 0);
    }

    // LayerNorm in place
    ln_kernel<<<BT_, 256>>>(out, gamma, beta);
}

// round 11
// speedup vs baseline: 1.0046x; 1.0046x over previous
#include <cuda_runtime.h>
#include <math.h>
#include <cstdint>

#define B_ 4
#define T_ 2048
#define E_ 1024
#define BT_ (B_*T_)
#define SEG_ 16
#define SEGL_ (T_/SEG_)   // 128

// ---------------- scratch (device globals; no allocation allowed) ----------
__device__ float g_ctx[BT_*E_];
__device__ float g_gated[BT_*E_];
__device__ float g_temporal[BT_*E_];
__device__ float g_gate[BT_*E_];
__device__ float g_sg[BT_*E_];
__device__ float g_h1[BT_*256];
__device__ float g_mod[BT_*4];
__device__ float g_seg[B_*SEG_*E_];
__device__ float g_seg4[4*B_*SEG_*E_];
__device__ float g_xr[BT_*E_];
__device__ float g_wgr[E_*2*E_];
__device__ float g_wn1r[256*E_];
__device__ float g_wtr[E_*E_];
__device__ float g_wsr[E_*E_];
__device__ float g_wor[E_*E_];

// ---------------- helpers --------------------------------------------------
__device__ __forceinline__ float sigmoidf_(float x) { return 1.0f / (1.0f + expf(-x)); }
__device__ __forceinline__ float geluf_(float x) {
    return 0.5f * x * (1.0f + erff(x * 0.70710678118654752440f));
}
__device__ __forceinline__ uint32_t to_tf32(float x) {
    uint32_t r;
    asm("cvt.rna.tf32.f32 %0, %1;" : "=r"(r) : "f"(x));
    return r;
}
__device__ __forceinline__ float tf32f(float x) { return __uint_as_float(to_tf32(x)); }

__device__ __forceinline__ uint32_t smem_u32(const void* p) {
    uint32_t a;
    asm("{ .reg .u64 t; cvta.to.shared.u64 t, %1; cvt.u32.u64 %0, t; }" : "=r"(a) : "l"(p));
    return a;
}

#define LDSM_X4(d, addr) \
    asm volatile("ldmatrix.sync.aligned.m8n8.x4.shared.b16 {%0,%1,%2,%3}, [%4];" \
                 : "=r"((d)[0]), "=r"((d)[1]), "=r"((d)[2]), "=r"((d)[3]) : "r"(addr))

#define CP_ASYNC16(dst, src) \
    asm volatile("cp.async.cg.shared.global [%0], [%1], 16;" :: "r"(dst), "l"(src))

// ============================================================================
// Launch 1: ema_ctx_p1 fused with round_x (reads x once; writes xr + seg)
// ============================================================================
__global__ void ema_ctx_p1_roundx(const float* __restrict__ x,
                                  const float* __restrict__ tau_ctx,
                                  float* __restrict__ seg,
                                  float* __restrict__ xr) {
    int tid = blockIdx.x * blockDim.x + threadIdx.x;
    if (tid >= B_ * E_ * SEG_) return;
    int e = tid & (E_ - 1);
    int s = (tid >> 10) & (SEG_ - 1);
    int b = tid >> 14;
    float alpha = 1.0f / (1.0f + expf(tau_ctx[0]));
    size_t base = ((size_t)(b * T_ + s * SEGL_)) * E_ + e;
    float h = 0.0f;
    for (int t = 0; t < SEGL_; t += 8) {
        float v[8];
#pragma unroll
        for (int i = 0; i < 8; i++) v[i] = __ldg(&x[base + (size_t)(t + i) * E_]);
#pragma unroll
        for (int i = 0; i < 8; i++) {
            h = fmaf(alpha, h, v[i]);
            xr[base + (size_t)(t + i) * E_] = tf32f(v[i]);
        }
    }
    seg[(b * SEG_ + s) * E_ + e] = h;
}

// ============================================================================
// Launch 2: ema_ctx_p2 carry scan fused with round_w
// ============================================================================
__global__ void ema_ctx_p2_roundw(const float* __restrict__ tau_ctx,
                                  float* __restrict__ seg,
                                  const float* __restrict__ Wg,  const float* __restrict__ Wn1,
                                  const float* __restrict__ Wt,  const float* __restrict__ Ws,
                                  const float* __restrict__ Wo,
                                  float* __restrict__ wgr, float* __restrict__ wn1r,
                                  float* __restrict__ wtr, float* __restrict__ wsr,
                                  float* __restrict__ wor) {
    int tid = blockIdx.x * blockDim.x + threadIdx.x;
    if (tid < B_ * E_) {
        int e = tid & (E_ - 1);
        int b = tid >> 10;
        float alpha = 1.0f / (1.0f + expf(tau_ctx[0]));
        float aL = 1.0f;
        for (int k = 0; k < SEGL_; k++) aL *= alpha;
        float carry = 0.0f;
        for (int s = 0; s < SEG_; s++) {
            size_t idx = (size_t)(b * SEG_ + s) * E_ + e;
            float Es = seg[idx];
            seg[idx] = carry;
            carry = fmaf(aL, carry, Es);
        }
    }
    const int n_wg  = E_ * 2 * E_ / 4;
    const int n_wn1 = 256 * E_ / 4;
    const int n_w   = E_ * E_ / 4;
    const int total = n_wg + n_wn1 + 3 * n_w;
    int stride = gridDim.x * blockDim.x;
    for (int i = tid; i < total; i += stride) {
        const float* src; float* dst; int j = i;
        if (j < n_wg) { src = Wg; dst = wgr; }
        else {
            j -= n_wg;
            if (j < n_wn1) { src = Wn1; dst = wn1r; }
            else {
                j -= n_wn1;
                int k = j / n_w; j -= k * n_w;
                src = (k == 0) ? Wt : (k == 1) ? Ws : Wo;
                dst = (k == 0) ? wtr : (k == 1) ? wsr : wor;
            }
        }
        float4 v = reinterpret_cast<const float4*>(src)[j];
        v.x = tf32f(v.x); v.y = tf32f(v.y); v.z = tf32f(v.z); v.w = tf32f(v.w);
        reinterpret_cast<float4*>(dst)[j] = v;
    }
}

// ============================================================================
// Launch 3: ema_ctx_p3 — replay with carry, store tf32-rounded ctx
// ============================================================================
__global__ void ema_ctx_p3(const float* __restrict__ x,
                           const float* __restrict__ tau_ctx,
                           const float* __restrict__ seg,
                           float* __restrict__ ctx) {
    int tid = blockIdx.x * blockDim.x + threadIdx.x;
    if (tid >= B_ * E_ * SEG_) return;
    int e = tid & (E_ - 1);
    int s = (tid >> 10) & (SEG_ - 1);
    int b = tid >> 14;
    float alpha = 1.0f / (1.0f + expf(tau_ctx[0]));
    size_t base = ((size_t)(b * T_ + s * SEGL_)) * E_ + e;
    float h = seg[(b * SEG_ + s) * E_ + e];
    for (int t = 0; t < SEGL_; t += 8) {
        float v[8];
#pragma unroll
        for (int i = 0; i < 8; i++) v[i] = __ldg(&x[base + (size_t)(t + i) * E_]);
#pragma unroll
        for (int i = 0; i < 8; i++) {
            h = fmaf(alpha, h, v[i]);
            ctx[base + (size_t)(t + i) * E_] = tf32f(h);
        }
    }
}

// ============================================================================
// Segmented EMA for the 4 modulated traces + softmax blend
// ============================================================================
__global__ void ema_tr_p1(const float* __restrict__ gated,
                          const float* __restrict__ mod,
                          const float* __restrict__ tau_raws,
                          float* __restrict__ seg4) {
    int tid = blockIdx.x * blockDim.x + threadIdx.x;
    if (tid >= B_ * E_ * SEG_) return;
    int e = tid & (E_ - 1);
    int s = (tid >> 10) & (SEG_ - 1);
    int b = tid >> 14;
    float al[4];
#pragma unroll
    for (int d = 0; d < 4; d++) al[d] = 1.0f / (1.0f + expf(tau_raws[d]));
    size_t base = ((size_t)(b * T_ + s * SEGL_)) * E_ + e;
    const float4* mod4 = reinterpret_cast<const float4*>(mod);
    size_t mbase = (size_t)b * T_ + s * SEGL_;
    float h0 = 0.f, h1 = 0.f, h2 = 0.f, h3 = 0.f;
    for (int t = 0; t < SEGL_; t += 4) {
        float g[4]; float4 mm[4];
#pragma unroll
        for (int i = 0; i < 4; i++) {
            g[i]  = __ldg(&gated[base + (size_t)(t + i) * E_]);
            mm[i] = __ldg(&mod4[mbase + t + i]);
        }
#pragma unroll
        for (int i = 0; i < 4; i++) {
            h0 = fmaf(al[0], h0, g[i] * mm[i].x);
            h1 = fmaf(al[1], h1, g[i] * mm[i].y);
            h2 = fmaf(al[2], h2, g[i] * mm[i].z);
            h3 = fmaf(al[3], h3, g[i] * mm[i].w);
        }
    }
    size_t o = (size_t)(b * SEG_ + s) * E_ + e;
    seg4[0 * (B_*SEG_*E_) + o] = h0;
    seg4[1 * (B_*SEG_*E_) + o] = h1;
    seg4[2 * (B_*SEG_*E_) + o] = h2;
    seg4[3 * (B_*SEG_*E_) + o] = h3;
}

__global__ void ema_tr_p2(const float* __restrict__ tau_raws,
                          float* __restrict__ seg4) {
    int tid = blockIdx.x * blockDim.x + threadIdx.x;
    if (tid >= B_ * E_) return;
    int e = tid & (E_ - 1);
    int b = tid >> 10;
#pragma unroll
    for (int d = 0; d < 4; d++) {
        float alpha = 1.0f / (1.0f + expf(tau_raws[d]));
        float aL = 1.0f;
        for (int k = 0; k < SEGL_; k++) aL *= alpha;
        float carry = 0.0f;
        for (int s = 0; s < SEG_; s++) {
            size_t idx = (size_t)d * (B_*SEG_*E_) + (size_t)(b * SEG_ + s) * E_ + e;
            float Es = seg4[idx];
            seg4[idx] = carry;
            carry = fmaf(aL, carry, Es);
        }
    }
}

// temporal only feeds the Wtemp GEMM -> store tf32-rounded
__global__ void ema_tr_p3(const float* __restrict__ gated,
                          const float* __restrict__ mod,
                          const float* __restrict__ tau_raws,
                          const float* __restrict__ blend,
                          const float* __restrict__ seg4,
                          float* __restrict__ temporal) {
    int tid = blockIdx.x * blockDim.x + threadIdx.x;
    if (tid >= B_ * E_ * SEG_) return;
    int e = tid & (E_ - 1);
    int s = (tid >> 10) & (SEG_ - 1);
    int b = tid >> 14;

    float al[4];
#pragma unroll
    for (int d = 0; d < 4; d++) al[d] = 1.0f / (1.0f + expf(tau_raws[d]));

    float bl[4];
#pragma unroll
    for (int d = 0; d < 4; d++) bl[d] = blend[d * E_ + e];
    float mx = fmaxf(fmaxf(bl[0], bl[1]), fmaxf(bl[2], bl[3]));
    float bw[4], sum = 0.0f;
#pragma unroll
    for (int d = 0; d < 4; d++) { bw[d] = expf(bl[d] - mx); sum += bw[d]; }
    float inv = 1.0f / sum;
#pragma unroll
    for (int d = 0; d < 4; d++) bw[d] *= inv;

    size_t base = ((size_t)(b * T_ + s * SEGL_)) * E_ + e;
    const float4* mod4 = reinterpret_cast<const float4*>(mod);
    size_t mbase = (size_t)b * T_ + s * SEGL_;
    size_t o = (size_t)(b * SEG_ + s) * E_ + e;
    float h0 = seg4[0 * (B_*SEG_*E_) + o];
    float h1 = seg4[1 * (B_*SEG_*E_) + o];
    float h2 = seg4[2 * (B_*SEG_*E_) + o];
    float h3 = seg4[3 * (B_*SEG_*E_) + o];

    for (int t = 0; t < SEGL_; t += 4) {
        float g[4]; float4 mm[4];
#pragma unroll
        for (int i = 0; i < 4; i++) {
            g[i]  = __ldg(&gated[base + (size_t)(t + i) * E_]);
            mm[i] = __ldg(&mod4[mbase + t + i]);
        }
#pragma unroll
        for (int i = 0; i < 4; i++) {
            h0 = fmaf(al[0], h0, g[i] * mm[i].x);
            h1 = fmaf(al[1], h1, g[i] * mm[i].y);
            h2 = fmaf(al[2], h2, g[i] * mm[i].z);
            h3 = fmaf(al[3], h3, g[i] * mm[i].w);
            temporal[base + (size_t)(t + i) * E_] =
                tf32f(bw[0] * h0 + bw[1] * h1 + bw[2] * h2 + bw[3] * h3);
        }
    }
}

// ============================================================================
// tf32 mma.sync GEMM, cp.async 3-stage pipeline + swizzled k-major + ldmatrix
// CTA 128x128, 4 WARPS of 64x64 (A/B smem redundancy 2x/2x instead of 4x/2x;
// LDS bytes per chunk 96KB -> 64KB), 128 threads, 2 CTAs/SM.
// mode: 0 none, 1 sigmoid(.)*extra, 2 gelu, 3 sigmoid, 4 gelu(.)*extra+round
// ============================================================================
static constexpr int STAGE_BYTES = 32768;    // A 16KB + B 16KB
static constexpr int NSTAGE = 3;
static constexpr int LDC = 132;
static constexpr int DYN_SMEM = NSTAGE * STAGE_BYTES;  // 98304 (>= 128*132*4)

__global__ void __launch_bounds__(128, 2)
gemm_mma(const float* __restrict__ A, const float* __restrict__ A2, int KA,
         const float* __restrict__ W, const float* __restrict__ bias,
         const float* __restrict__ extra, float* __restrict__ C,
         int N, int K, int mode) {
    extern __shared__ float smem[];
    uint32_t sb = smem_u32(smem);
    int tid = threadIdx.x, wid = tid >> 5, lane = tid & 31;
    int bm = blockIdx.y * 128, bn = blockIdx.x * 128;
    int wm = wid & 1;        // M half (64 rows)
    int wn = wid >> 1;       // N half (64 cols)

    float acc[4][8][4];
#pragma unroll
    for (int i = 0; i < 4; i++)
#pragma unroll
        for (int j = 0; j < 8; j++)
#pragma unroll
            for (int r = 0; r < 4; r++) acc[i][j][r] = 0.0f;

    const int NC = K / 32;

    int p7 = lane & 7;
    uint32_t aRow[4], bRow[4];
#pragma unroll
    for (int i = 0; i < 4; i++)
        aRow[i] = (uint32_t)(wm * 64 + i * 16 + p7 + 8 * ((lane >> 3) & 1)) * 128u;
#pragma unroll
    for (int j2 = 0; j2 < 4; j2++)
        bRow[j2] = (uint32_t)(wn * 64 + j2 * 16 + p7 + 8 * (lane >> 4)) * 128u;
    uint32_t swzA[4], swzB[4];
#pragma unroll
    for (int ks = 0; ks < 4; ks++) {
        swzA[ks] = (uint32_t)(((ks * 2 + (lane >> 4)) ^ p7) * 16);
        swzB[ks] = (uint32_t)(((ks * 2 + ((lane >> 3) & 1)) ^ p7) * 16);
    }

    auto load_chunk = [&](int c, int s) {
        int k0 = c * 32;
        const float* srcA = A; int ka = k0;
        if (A2 != nullptr && k0 >= KA) { srcA = A2; ka = k0 - KA; }
        uint32_t dstA = sb + (uint32_t)s * STAGE_BYTES;
        uint32_t dstB = dstA + 16384;
#pragma unroll
        for (int q = 0; q < 8; q++) {
            int idx = tid + q * 128;          // 0..1023
            int row = idx >> 3, ch = idx & 7;
            uint32_t off = (uint32_t)row * 128u + (uint32_t)((ch ^ (row & 7)) * 16);
            const float* sA = srcA + (size_t)(bm + row) * KA + ka + ch * 4;
            CP_ASYNC16(dstA + off, sA);
            const float* sB = W + (size_t)(bn + row) * K + k0 + ch * 4;
            CP_ASYNC16(dstB + off, sB);
        }
        asm volatile("cp.async.commit_group;" ::: "memory");
    };

    load_chunk(0, 0);
    load_chunk(1, 1);

    for (int c = 0; c < NC; c++) {
        int s = c % NSTAGE;
        if (c < NC - 1) asm volatile("cp.async.wait_group 1;" ::: "memory");
        else            asm volatile("cp.async.wait_group 0;" ::: "memory");
        __syncthreads();
        if (c + 2 < NC) load_chunk(c + 2, (c + 2) % NSTAGE);

        uint32_t baseA = sb + (uint32_t)s * STAGE_BYTES;
        uint32_t baseB = baseA + 16384;
#pragma unroll
        for (int ks = 0; ks < 4; ks++) {
            uint32_t a[4][4], b[4][4];
#pragma unroll
            for (int i = 0; i < 4; i++) LDSM_X4(a[i], baseA + aRow[i] + swzA[ks]);
#pragma unroll
            for (int j2 = 0; j2 < 4; j2++) LDSM_X4(b[j2], baseB + bRow[j2] + swzB[ks]);
#pragma unroll
            for (int i = 0; i < 4; i++)
#pragma unroll
                for (int j = 0; j < 8; j++) {
                    asm volatile(
                        "mma.sync.aligned.m16n8k8.row.col.f32.tf32.tf32.f32 "
                        "{%0,%1,%2,%3}, {%4,%5,%6,%7}, {%8,%9}, {%0,%1,%2,%3};"
                        : "+f"(acc[i][j][0]), "+f"(acc[i][j][1]),
                          "+f"(acc[i][j][2]), "+f"(acc[i][j][3])
                        : "r"(a[i][0]), "r"(a[i][1]), "r"(a[i][2]), "r"(a[i][3]),
                          "r"(b[j >> 1][(j & 1) * 2]), "r"(b[j >> 1][(j & 1) * 2 + 1]));
                }
        }
    }
    __syncthreads();

    // -------- epilogue: acc frags -> smem -> fused activation -> float4 STG --
    float* Cs = smem;
#pragma unroll
    for (int i = 0; i < 4; i++)
#pragma unroll
        for (int j = 0; j < 8; j++) {
            int r0 = wm * 64 + i * 16 + (lane >> 2);
            int c0 = wn * 64 + j * 8 + (lane & 3) * 2;
            *reinterpret_cast<float2*>(Cs + r0 * LDC + c0) =
                make_float2(acc[i][j][0], acc[i][j][1]);
            *reinterpret_cast<float2*>(Cs + (r0 + 8) * LDC + c0) =
                make_float2(acc[i][j][2], acc[i][j][3]);
        }
    __syncthreads();

    for (int t = tid; t < 128 * 32; t += 128) {
        int r = t >> 5, c0 = (t & 31) * 4;
        const float* rg = Cs + r * LDC + c0;
        int m = bm + r, n = bn + c0;
        size_t oidx = (size_t)m * N + n;
        float v[4];
#pragma unroll
        for (int i = 0; i < 4; i++) {
            v[i] = rg[i];
            if (bias != nullptr) v[i] += __ldg(&bias[n + i]);
        }
        if (mode == 1 || mode == 4) {
            float4 ex = *reinterpret_cast<const float4*>(extra + oidx);
            float exv[4] = {ex.x, ex.y, ex.z, ex.w};
#pragma unroll
            for (int i = 0; i < 4; i++)
                v[i] = (mode == 1) ? sigmoidf_(v[i]) * exv[i]
                                   : tf32f(geluf_(v[i]) * exv[i]);
        } else if (mode == 2) {
#pragma unroll
            for (int i = 0; i < 4; i++) v[i] = geluf_(v[i]);
        } else if (mode == 3) {
#pragma unroll
            for (int i = 0; i < 4; i++) v[i] = sigmoidf_(v[i]);
        }
        *reinterpret_cast<float4*>(C + oidx) = make_float4(v[0], v[1], v[2], v[3]);
    }
}

// ---------------- mod = 0.5 + sigmoid(h1 @ Wn2^T + bn2) ---------------------
__global__ void mod_kernel(const float* __restrict__ h1,
                           const float* __restrict__ Wn2,
                           const float* __restrict__ bn2,
                           float* __restrict__ mod) {
    int warp = (blockIdx.x * blockDim.x + threadIdx.x) >> 5;
    int lane = threadIdx.x & 31;
    if (warp >= BT_) return;
    const float* hr = h1 + (size_t)warp * 256;
    float a0 = 0.f, a1 = 0.f, a2 = 0.f, a3 = 0.f;
    for (int k = lane; k < 256; k += 32) {
        float hv = __ldg(&hr[k]);
        a0 = fmaf(hv, __ldg(&Wn2[k]),       a0);
        a1 = fmaf(hv, __ldg(&Wn2[256 + k]), a1);
        a2 = fmaf(hv, __ldg(&Wn2[512 + k]), a2);
        a3 = fmaf(hv, __ldg(&Wn2[768 + k]), a3);
    }
#pragma unroll
    for (int o = 16; o > 0; o >>= 1) {
        a0 += __shfl_xor_sync(0xffffffff, a0, o);
        a1 += __shfl_xor_sync(0xffffffff, a1, o);
        a2 += __shfl_xor_sync(0xffffffff, a2, o);
        a3 += __shfl_xor_sync(0xffffffff, a3, o);
    }
    if (lane == 0) {
        mod[(size_t)warp * 4 + 0] = 0.5f + sigmoidf_(a0 + bn2[0]);
        mod[(size_t)warp * 4 + 1] = 0.5f + sigmoidf_(a1 + bn2[1]);
        mod[(size_t)warp * 4 + 2] = 0.5f + sigmoidf_(a2 + bn2[2]);
        mod[(size_t)warp * 4 + 3] = 0.5f + sigmoidf_(a3 + bn2[3]);
    }
}

// ---------------- in-place LayerNorm over E per row --------------------------
__global__ void ln_kernel(float* __restrict__ out,
                          const float* __restrict__ gamma,
                          const float* __restrict__ beta) {
    int row = blockIdx.x;
    float* p = out + (size_t)row * E_;
    int tid = threadIdx.x;
    float v[4];
    float s = 0.f, ss = 0.f;
#pragma unroll
    for (int i = 0; i < 4; i++) {
        v[i] = p[tid + i * 256];
        s += v[i];
        ss += v[i] * v[i];
    }
#pragma unroll
    for (int o = 16; o > 0; o >>= 1) {
        s  += __shfl_down_sync(0xffffffff, s,  o);
        ss += __shfl_down_sync(0xffffffff, ss, o);
    }
    __shared__ float shs[8], shss[8];
    __shared__ float mu_s, inv_s;
    int wid = tid >> 5, lane = tid & 31;
    if (lane == 0) { shs[wid] = s; shss[wid] = ss; }
    __syncthreads();
    if (tid == 0) {
        float S = 0.f, SS = 0.f;
#pragma unroll
        for (int w = 0; w < 8; w++) { S += shs[w]; SS += shss[w]; }
        float mu  = S / (float)E_;
        float var = SS / (float)E_ - mu * mu;
        mu_s = mu;
        inv_s = rsqrtf(var + 1e-5f);
    }
    __syncthreads();
    float mu = mu_s, iv = inv_s;
#pragma unroll
    for (int i = 0; i < 4; i++) {
        int c = tid + i * 256;
        p[c] = (v[i] - mu) * iv * __ldg(&gamma[c]) + __ldg(&beta[c]);
    }
}

// ---------------- launch -----------------------------------------------------
extern "C" void kernel_launch(void* const* d_in, const int* in_sizes, int n_in,
                              void* d_out, int out_size) {
    const float* x        = (const float*)d_in[0];
    const float* tau_ctx  = (const float*)d_in[1];
    const float* tau_raws = (const float*)d_in[2];
    const float* Wg       = (const float*)d_in[3];
    const float* bg       = (const float*)d_in[4];
    const float* Wn1      = (const float*)d_in[5];
    const float* bn1      = (const float*)d_in[6];
    const float* Wn2      = (const float*)d_in[7];
    const float* bn2      = (const float*)d_in[8];
    const float* blend    = (const float*)d_in[9];
    const float* Wsoma    = (const float*)d_in[10];
    const float* bsoma    = (const float*)d_in[11];
    const float* Wtemp    = (const float*)d_in[12];
    const float* btemp    = (const float*)d_in[13];
    const float* Wout     = (const float*)d_in[14];
    const float* gamma    = (const float*)d_in[15];
    const float* beta     = (const float*)d_in[16];
    float* out = (float*)d_out;

    float *ctx, *gated, *temporal, *gate, *sg, *h1, *mod, *seg, *seg4;
    float *xr, *wgr, *wn1r, *wtr, *wsr, *wor;
    cudaGetSymbolAddress((void**)&ctx,      g_ctx);
    cudaGetSymbolAddress((void**)&gated,    g_gated);
    cudaGetSymbolAddress((void**)&temporal, g_temporal);
    cudaGetSymbolAddress((void**)&gate,     g_gate);
    cudaGetSymbolAddress((void**)&sg,       g_sg);
    cudaGetSymbolAddress((void**)&h1,       g_h1);
    cudaGetSymbolAddress((void**)&mod,      g_mod);
    cudaGetSymbolAddress((void**)&seg,      g_seg);
    cudaGetSymbolAddress((void**)&seg4,     g_seg4);
    cudaGetSymbolAddress((void**)&xr,       g_xr);
    cudaGetSymbolAddress((void**)&wgr,      g_wgr);
    cudaGetSymbolAddress((void**)&wn1r,     g_wn1r);
    cudaGetSymbolAddress((void**)&wtr,      g_wtr);
    cudaGetSymbolAddress((void**)&wsr,      g_wsr);
    cudaGetSymbolAddress((void**)&wor,      g_wor);

    cudaFuncSetAttribute(gemm_mma, cudaFuncAttributeMaxDynamicSharedMemorySize, DYN_SMEM);
    cudaFuncSetAttribute(gemm_mma, cudaFuncAttributePreferredSharedMemoryCarveout,
                         cudaSharedmemCarveoutMaxShared);

    const int NSEG_T = B_ * E_ * SEG_;

    // launch 1: ema_ctx p1 + round_x
    ema_ctx_p1_roundx<<<NSEG_T / 256, 256>>>(x, tau_ctx, seg, xr);
    // launch 2: ema_ctx p2 carry scan + round_w
    ema_ctx_p2_roundw<<<1024, 256>>>(tau_ctx, seg, Wg, Wn1, Wtemp, Wsoma, Wout,
                                     wgr, wn1r, wtr, wsr, wor);
    // launch 3: ema_ctx p3 -> ctx
    ema_ctx_p3<<<NSEG_T / 256, 256>>>(x, tau_ctx, seg, ctx);

    // launch 4 (ncu captures this): gated = x * sigmoid([x,ctx]@Wg^T + bg)
    {
        dim3 grid(E_ / 128, BT_ / 128);
        gemm_mma<<<grid, 128, DYN_SMEM>>>(xr, ctx, E_, wgr, bg, x, gated, E_, 2 * E_, 1);
    }

    // h1 = gelu(x @ Wn1^T + bn1)
    {
        dim3 grid(256 / 128, BT_ / 128);
        gemm_mma<<<grid, 128, DYN_SMEM>>>(xr, nullptr, E_, wn1r, bn1, nullptr, h1, 256, E_, 2);
    }

    // mod = 0.5 + sigmoid(h1 @ Wn2^T + bn2)
    mod_kernel<<<(BT_ * 32) / 256, 256>>>(h1, Wn2, bn2, mod);

    // temporal — segmented 3-pass over 4 chains + blend
    ema_tr_p1<<<NSEG_T / 256, 256>>>(gated, mod, tau_raws, seg4);
    ema_tr_p2<<<(B_ * E_) / 256, 256>>>(tau_raws, seg4);
    ema_tr_p3<<<NSEG_T / 256, 256>>>(gated, mod, tau_raws, blend, seg4, temporal);

    // gate = sigmoid(temporal @ Wtemp^T + btemp)
    {
        dim3 grid(E_ / 128, BT_ / 128);
        gemm_mma<<<grid, 128, DYN_SMEM>>>(temporal, nullptr, E_, wtr, btemp, nullptr, gate, E_, E_, 3);
    }

    // sg = gelu(x @ Wsoma^T + bsoma) * gate
    {
        dim3 grid(E_ / 128, BT_ / 128);
        gemm_mma<<<grid, 128, DYN_SMEM>>>(xr, nullptr, E_, wsr, bsoma, gate, sg, E_, E_, 4);
    }

    // out = sg @ Wout^T
    {
        dim3 grid(E_ / 128, BT_ / 128);
        gemm_mma<<<grid, 128, DYN_SMEM>>>(sg, nullptr, E_, wor, nullptr, nullptr, out, E_, E_, 0);
    }

    // LayerNorm in place
    ln_kernel<<<BT_, 256>>>(out, gamma, beta);
}

// round 12
// speedup vs baseline: 1.1016x; 1.0965x over previous
#include <cuda_runtime.h>
#include <math.h>
#include <cstdint>

#define B_ 4
#define T_ 2048
#define E_ 1024
#define BT_ (B_*T_)
#define SEG_ 16
#define SEGL_ (T_/SEG_)   // 128

// ---------------- scratch (device globals; no allocation allowed) ----------
__device__ float g_ctx[BT_*E_];
__device__ float g_gated[BT_*E_];
__device__ float g_temporal[BT_*E_];
__device__ float g_gate[BT_*E_];
__device__ float g_sg[BT_*E_];
__device__ float g_h1[BT_*256];
__device__ float g_mod[BT_*4];
__device__ float g_seg[B_*SEG_*E_];
__device__ float g_seg4[4*B_*SEG_*E_];
__device__ float g_xr[BT_*E_];
__device__ float g_wgr[E_*2*E_];
__device__ float g_wn1r[256*E_];
__device__ float g_wtr[E_*E_];
__device__ float g_wsr[E_*E_];
__device__ float g_wor[E_*E_];

// ---------------- helpers --------------------------------------------------
__device__ __forceinline__ float sigmoidf_(float x) { return 1.0f / (1.0f + expf(-x)); }
__device__ __forceinline__ float geluf_(float x) {
    return 0.5f * x * (1.0f + erff(x * 0.70710678118654752440f));
}
__device__ __forceinline__ uint32_t to_tf32(float x) {
    uint32_t r;
    asm("cvt.rna.tf32.f32 %0, %1;" : "=r"(r) : "f"(x));
    return r;
}
__device__ __forceinline__ float tf32f(float x) { return __uint_as_float(to_tf32(x)); }

__device__ __forceinline__ uint32_t smem_u32(const void* p) {
    uint32_t a;
    asm("{ .reg .u64 t; cvta.to.shared.u64 t, %1; cvt.u32.u64 %0, t; }" : "=r"(a) : "l"(p));
    return a;
}

#define LDSM_X4(d, addr) \
    asm volatile("ldmatrix.sync.aligned.m8n8.x4.shared.b16 {%0,%1,%2,%3}, [%4];" \
                 : "=r"((d)[0]), "=r"((d)[1]), "=r"((d)[2]), "=r"((d)[3]) : "r"(addr))

#define CP_ASYNC16(dst, src) \
    asm volatile("cp.async.cg.shared.global [%0], [%1], 16;" :: "r"(dst), "l"(src))

// ============================================================================
// s0 Launch 1: ema_ctx_p1 fused with round_x (reads x once; writes xr + seg)
// ============================================================================
__global__ void ema_ctx_p1_roundx(const float* __restrict__ x,
                                  const float* __restrict__ tau_ctx,
                                  float* __restrict__ seg,
                                  float* __restrict__ xr) {
    int tid = blockIdx.x * blockDim.x + threadIdx.x;
    if (tid >= B_ * E_ * SEG_) return;
    int e = tid & (E_ - 1);
    int s = (tid >> 10) & (SEG_ - 1);
    int b = tid >> 14;
    float alpha = 1.0f / (1.0f + expf(tau_ctx[0]));
    size_t base = ((size_t)(b * T_ + s * SEGL_)) * E_ + e;
    float h = 0.0f;
    for (int t = 0; t < SEGL_; t += 8) {
        float v[8];
#pragma unroll
        for (int i = 0; i < 8; i++) v[i] = __ldg(&x[base + (size_t)(t + i) * E_]);
#pragma unroll
        for (int i = 0; i < 8; i++) {
            h = fmaf(alpha, h, v[i]);
            xr[base + (size_t)(t + i) * E_] = tf32f(v[i]);
        }
    }
    seg[(b * SEG_ + s) * E_ + e] = h;
}

// ============================================================================
// s1: round Wn1 + Wsoma (the second-stream GEMM weights)
// ============================================================================
__global__ void round_w2(const float* __restrict__ Wn1, const float* __restrict__ Ws,
                         float* __restrict__ wn1r, float* __restrict__ wsr) {
    const int n_wn1 = 256 * E_ / 4;
    const int n_w   = E_ * E_ / 4;
    const int total = n_wn1 + n_w;
    int i = blockIdx.x * blockDim.x + threadIdx.x;
    int stride = gridDim.x * blockDim.x;
    for (; i < total; i += stride) {
        const float* src; float* dst; int j = i;
        if (j < n_wn1) { src = Wn1; dst = wn1r; }
        else { j -= n_wn1; src = Ws; dst = wsr; }
        float4 v = reinterpret_cast<const float4*>(src)[j];
        v.x = tf32f(v.x); v.y = tf32f(v.y); v.z = tf32f(v.z); v.w = tf32f(v.w);
        reinterpret_cast<float4*>(dst)[j] = v;
    }
}

// ============================================================================
// s0 Launch: ema_ctx_p2 carry scan fused with rounding Wg/Wtemp/Wout
// ============================================================================
__global__ void ema_ctx_p2_roundw(const float* __restrict__ tau_ctx,
                                  float* __restrict__ seg,
                                  const float* __restrict__ Wg,
                                  const float* __restrict__ Wt,
                                  const float* __restrict__ Wo,
                                  float* __restrict__ wgr,
                                  float* __restrict__ wtr,
                                  float* __restrict__ wor) {
    int tid = blockIdx.x * blockDim.x + threadIdx.x;
    if (tid < B_ * E_) {
        int e = tid & (E_ - 1);
        int b = tid >> 10;
        float alpha = 1.0f / (1.0f + expf(tau_ctx[0]));
        float aL = 1.0f;
        for (int k = 0; k < SEGL_; k++) aL *= alpha;
        float carry = 0.0f;
        for (int s = 0; s < SEG_; s++) {
            size_t idx = (size_t)(b * SEG_ + s) * E_ + e;
            float Es = seg[idx];
            seg[idx] = carry;
            carry = fmaf(aL, carry, Es);
        }
    }
    const int n_wg = E_ * 2 * E_ / 4;
    const int n_w  = E_ * E_ / 4;
    const int total = n_wg + 2 * n_w;
    int stride = gridDim.x * blockDim.x;
    for (int i = tid; i < total; i += stride) {
        const float* src; float* dst; int j = i;
        if (j < n_wg) { src = Wg; dst = wgr; }
        else {
            j -= n_wg;
            if (j < n_w) { src = Wt; dst = wtr; }
            else { j -= n_w; src = Wo; dst = wor; }
        }
        float4 v = reinterpret_cast<const float4*>(src)[j];
        v.x = tf32f(v.x); v.y = tf32f(v.y); v.z = tf32f(v.z); v.w = tf32f(v.w);
        reinterpret_cast<float4*>(dst)[j] = v;
    }
}

// ============================================================================
// ema_ctx_p3 — replay with carry, store tf32-rounded ctx
// ============================================================================
__global__ void ema_ctx_p3(const float* __restrict__ x,
                           const float* __restrict__ tau_ctx,
                           const float* __restrict__ seg,
                           float* __restrict__ ctx) {
    int tid = blockIdx.x * blockDim.x + threadIdx.x;
    if (tid >= B_ * E_ * SEG_) return;
    int e = tid & (E_ - 1);
    int s = (tid >> 10) & (SEG_ - 1);
    int b = tid >> 14;
    float alpha = 1.0f / (1.0f + expf(tau_ctx[0]));
    size_t base = ((size_t)(b * T_ + s * SEGL_)) * E_ + e;
    float h = seg[(b * SEG_ + s) * E_ + e];
    for (int t = 0; t < SEGL_; t += 8) {
        float v[8];
#pragma unroll
        for (int i = 0; i < 8; i++) v[i] = __ldg(&x[base + (size_t)(t + i) * E_]);
#pragma unroll
        for (int i = 0; i < 8; i++) {
            h = fmaf(alpha, h, v[i]);
            ctx[base + (size_t)(t + i) * E_] = tf32f(h);
        }
    }
}

// ============================================================================
// Segmented EMA for the 4 modulated traces + softmax blend
// ============================================================================
__global__ void ema_tr_p1(const float* __restrict__ gated,
                          const float* __restrict__ mod,
                          const float* __restrict__ tau_raws,
                          float* __restrict__ seg4) {
    int tid = blockIdx.x * blockDim.x + threadIdx.x;
    if (tid >= B_ * E_ * SEG_) return;
    int e = tid & (E_ - 1);
    int s = (tid >> 10) & (SEG_ - 1);
    int b = tid >> 14;
    float al[4];
#pragma unroll
    for (int d = 0; d < 4; d++) al[d] = 1.0f / (1.0f + expf(tau_raws[d]));
    size_t base = ((size_t)(b * T_ + s * SEGL_)) * E_ + e;
    const float4* mod4 = reinterpret_cast<const float4*>(mod);
    size_t mbase = (size_t)b * T_ + s * SEGL_;
    float h0 = 0.f, h1 = 0.f, h2 = 0.f, h3 = 0.f;
    for (int t = 0; t < SEGL_; t += 4) {
        float g[4]; float4 mm[4];
#pragma unroll
        for (int i = 0; i < 4; i++) {
            g[i]  = __ldg(&gated[base + (size_t)(t + i) * E_]);
            mm[i] = __ldg(&mod4[mbase + t + i]);
        }
#pragma unroll
        for (int i = 0; i < 4; i++) {
            h0 = fmaf(al[0], h0, g[i] * mm[i].x);
            h1 = fmaf(al[1], h1, g[i] * mm[i].y);
            h2 = fmaf(al[2], h2, g[i] * mm[i].z);
            h3 = fmaf(al[3], h3, g[i] * mm[i].w);
        }
    }
    size_t o = (size_t)(b * SEG_ + s) * E_ + e;
    seg4[0 * (B_*SEG_*E_) + o] = h0;
    seg4[1 * (B_*SEG_*E_) + o] = h1;
    seg4[2 * (B_*SEG_*E_) + o] = h2;
    seg4[3 * (B_*SEG_*E_) + o] = h3;
}

__global__ void ema_tr_p2(const float* __restrict__ tau_raws,
                          float* __restrict__ seg4) {
    int tid = blockIdx.x * blockDim.x + threadIdx.x;
    if (tid >= B_ * E_) return;
    int e = tid & (E_ - 1);
    int b = tid >> 10;
#pragma unroll
    for (int d = 0; d < 4; d++) {
        float alpha = 1.0f / (1.0f + expf(tau_raws[d]));
        float aL = 1.0f;
        for (int k = 0; k < SEGL_; k++) aL *= alpha;
        float carry = 0.0f;
        for (int s = 0; s < SEG_; s++) {
            size_t idx = (size_t)d * (B_*SEG_*E_) + (size_t)(b * SEG_ + s) * E_ + e;
            float Es = seg4[idx];
            seg4[idx] = carry;
            carry = fmaf(aL, carry, Es);
        }
    }
}

// temporal only feeds the Wtemp GEMM -> store tf32-rounded
__global__ void ema_tr_p3(const float* __restrict__ gated,
                          const float* __restrict__ mod,
                          const float* __restrict__ tau_raws,
                          const float* __restrict__ blend,
                          const float* __restrict__ seg4,
                          float* __restrict__ temporal) {
    int tid = blockIdx.x * blockDim.x + threadIdx.x;
    if (tid >= B_ * E_ * SEG_) return;
    int e = tid & (E_ - 1);
    int s = (tid >> 10) & (SEG_ - 1);
    int b = tid >> 14;

    float al[4];
#pragma unroll
    for (int d = 0; d < 4; d++) al[d] = 1.0f / (1.0f + expf(tau_raws[d]));

    float bl[4];
#pragma unroll
    for (int d = 0; d < 4; d++) bl[d] = blend[d * E_ + e];
    float mx = fmaxf(fmaxf(bl[0], bl[1]), fmaxf(bl[2], bl[3]));
    float bw[4], sum = 0.0f;
#pragma unroll
    for (int d = 0; d < 4; d++) { bw[d] = expf(bl[d] - mx); sum += bw[d]; }
    float inv = 1.0f / sum;
#pragma unroll
    for (int d = 0; d < 4; d++) bw[d] *= inv;

    size_t base = ((size_t)(b * T_ + s * SEGL_)) * E_ + e;
    const float4* mod4 = reinterpret_cast<const float4*>(mod);
    size_t mbase = (size_t)b * T_ + s * SEGL_;
    size_t o = (size_t)(b * SEG_ + s) * E_ + e;
    float h0 = seg4[0 * (B_*SEG_*E_) + o];
    float h1 = seg4[1 * (B_*SEG_*E_) + o];
    float h2 = seg4[2 * (B_*SEG_*E_) + o];
    float h3 = seg4[3 * (B_*SEG_*E_) + o];

    for (int t = 0; t < SEGL_; t += 4) {
        float g[4]; float4 mm[4];
#pragma unroll
        for (int i = 0; i < 4; i++) {
            g[i]  = __ldg(&gated[base + (size_t)(t + i) * E_]);
            mm[i] = __ldg(&mod4[mbase + t + i]);
        }
#pragma unroll
        for (int i = 0; i < 4; i++) {
            h0 = fmaf(al[0], h0, g[i] * mm[i].x);
            h1 = fmaf(al[1], h1, g[i] * mm[i].y);
            h2 = fmaf(al[2], h2, g[i] * mm[i].z);
            h3 = fmaf(al[3], h3, g[i] * mm[i].w);
            temporal[base + (size_t)(t + i) * E_] =
                tf32f(bw[0] * h0 + bw[1] * h1 + bw[2] * h2 + bw[3] * h3);
        }
    }
}

// ============================================================================
// tf32 mma.sync GEMM (R10 shape: 256thr, 8 warps 64x32, cp.async 3-stage,
// swizzled k-major + ldmatrix).
// mode: 0 none, 1 sigmoid(.)*extra, 2 gelu, 3 sigmoid,
//       5 tf32f(sigmoid(.)*extra)   (gate GEMM with extra = soma_raw)
// ============================================================================
static constexpr int STAGE_BYTES = 32768;
static constexpr int NSTAGE = 3;
static constexpr int LDC = 132;
static constexpr int DYN_SMEM = NSTAGE * STAGE_BYTES;  // 98304

__global__ void __launch_bounds__(256, 2)
gemm_mma(const float* __restrict__ A, const float* __restrict__ A2, int KA,
         const float* __restrict__ W, const float* __restrict__ bias,
         const float* __restrict__ extra, float* __restrict__ C,
         int N, int K, int mode) {
    extern __shared__ float smem[];
    uint32_t sb = smem_u32(smem);
    int tid = threadIdx.x, wid = tid >> 5, lane = tid & 31;
    int bm = blockIdx.y * 128, bn = blockIdx.x * 128;
    int wm = wid & 1;
    int wn = wid >> 1;

    float acc[4][4][4];
#pragma unroll
    for (int i = 0; i < 4; i++)
#pragma unroll
        for (int j = 0; j < 4; j++)
#pragma unroll
            for (int r = 0; r < 4; r++) acc[i][j][r] = 0.0f;

    const int NC = K / 32;

    int p7 = lane & 7;
    uint32_t aRow[4], bRow[2];
#pragma unroll
    for (int i = 0; i < 4; i++)
        aRow[i] = (uint32_t)(wm * 64 + i * 16 + p7 + 8 * ((lane >> 3) & 1)) * 128u;
#pragma unroll
    for (int j2 = 0; j2 < 2; j2++)
        bRow[j2] = (uint32_t)(wn * 32 + j2 * 16 + p7 + 8 * (lane >> 4)) * 128u;
    uint32_t swzA[4], swzB[4];
#pragma unroll
    for (int ks = 0; ks < 4; ks++) {
        swzA[ks] = (uint32_t)(((ks * 2 + (lane >> 4)) ^ p7) * 16);
        swzB[ks] = (uint32_t)(((ks * 2 + ((lane >> 3) & 1)) ^ p7) * 16);
    }

    auto load_chunk = [&](int c, int s) {
        int k0 = c * 32;
        const float* srcA = A; int ka = k0;
        if (A2 != nullptr && k0 >= KA) { srcA = A2; ka = k0 - KA; }
        uint32_t dstA = sb + (uint32_t)s * STAGE_BYTES;
        uint32_t dstB = dstA + 16384;
#pragma unroll
        for (int q = 0; q < 4; q++) {
            int idx = tid + q * 256;
            int row = idx >> 3, ch = idx & 7;
            uint32_t off = (uint32_t)row * 128u + (uint32_t)((ch ^ (row & 7)) * 16);
            const float* sA = srcA + (size_t)(bm + row) * KA + ka + ch * 4;
            CP_ASYNC16(dstA + off, sA);
            const float* sB = W + (size_t)(bn + row) * K + k0 + ch * 4;
            CP_ASYNC16(dstB + off, sB);
        }
        asm volatile("cp.async.commit_group;" ::: "memory");
    };

    load_chunk(0, 0);
    load_chunk(1, 1);

    for (int c = 0; c < NC; c++) {
        int s = c % NSTAGE;
        if (c < NC - 1) asm volatile("cp.async.wait_group 1;" ::: "memory");
        else            asm volatile("cp.async.wait_group 0;" ::: "memory");
        __syncthreads();
        if (c + 2 < NC) load_chunk(c + 2, (c + 2) % NSTAGE);

        uint32_t baseA = sb + (uint32_t)s * STAGE_BYTES;
        uint32_t baseB = baseA + 16384;
#pragma unroll
        for (int ks = 0; ks < 4; ks++) {
            uint32_t a[4][4], b[2][4];
#pragma unroll
            for (int i = 0; i < 4; i++) LDSM_X4(a[i], baseA + aRow[i] + swzA[ks]);
#pragma unroll
            for (int j2 = 0; j2 < 2; j2++) LDSM_X4(b[j2], baseB + bRow[j2] + swzB[ks]);
#pragma unroll
            for (int i = 0; i < 4; i++)
#pragma unroll
                for (int j = 0; j < 4; j++) {
                    asm volatile(
                        "mma.sync.aligned.m16n8k8.row.col.f32.tf32.tf32.f32 "
                        "{%0,%1,%2,%3}, {%4,%5,%6,%7}, {%8,%9}, {%0,%1,%2,%3};"
                        : "+f"(acc[i][j][0]), "+f"(acc[i][j][1]),
                          "+f"(acc[i][j][2]), "+f"(acc[i][j][3])
                        : "r"(a[i][0]), "r"(a[i][1]), "r"(a[i][2]), "r"(a[i][3]),
                          "r"(b[j >> 1][(j & 1) * 2]), "r"(b[j >> 1][(j & 1) * 2 + 1]));
                }
        }
    }
    __syncthreads();

    // -------- epilogue ----------------------------------------------------
    float* Cs = smem;
#pragma unroll
    for (int i = 0; i < 4; i++)
#pragma unroll
        for (int j = 0; j < 4; j++) {
            int r0 = wm * 64 + i * 16 + (lane >> 2);
            int c0 = wn * 32 + j * 8 + (lane & 3) * 2;
            *reinterpret_cast<float2*>(Cs + r0 * LDC + c0) =
                make_float2(acc[i][j][0], acc[i][j][1]);
            *reinterpret_cast<float2*>(Cs + (r0 + 8) * LDC + c0) =
                make_float2(acc[i][j][2], acc[i][j][3]);
        }
    __syncthreads();

    for (int t = tid; t < 128 * 32; t += 256) {
        int r = t >> 5, c0 = (t & 31) * 4;
        const float* rg = Cs + r * LDC + c0;
        int m = bm + r, n = bn + c0;
        size_t oidx = (size_t)m * N + n;
        float v[4];
#pragma unroll
        for (int i = 0; i < 4; i++) {
            v[i] = rg[i];
            if (bias != nullptr) v[i] += __ldg(&bias[n + i]);
        }
        if (mode == 1 || mode == 5) {
            float4 ex = *reinterpret_cast<const float4*>(extra + oidx);
            float exv[4] = {ex.x, ex.y, ex.z, ex.w};
#pragma unroll
            for (int i = 0; i < 4; i++) {
                float p = sigmoidf_(v[i]) * exv[i];
                v[i] = (mode == 1) ? p : tf32f(p);
            }
        } else if (mode == 2) {
#pragma unroll
            for (int i = 0; i < 4; i++) v[i] = geluf_(v[i]);
        } else if (mode == 3) {
#pragma unroll
            for (int i = 0; i < 4; i++) v[i] = sigmoidf_(v[i]);
        }
        *reinterpret_cast<float4*>(C + oidx) = make_float4(v[0], v[1], v[2], v[3]);
    }
}

// ---------------- mod = 0.5 + sigmoid(h1 @ Wn2^T + bn2) ---------------------
__global__ void mod_kernel(const float* __restrict__ h1,
                           const float* __restrict__ Wn2,
                           const float* __restrict__ bn2,
                           float* __restrict__ mod) {
    int warp = (blockIdx.x * blockDim.x + threadIdx.x) >> 5;
    int lane = threadIdx.x & 31;
    if (warp >= BT_) return;
    const float* hr = h1 + (size_t)warp * 256;
    float a0 = 0.f, a1 = 0.f, a2 = 0.f, a3 = 0.f;
    for (int k = lane; k < 256; k += 32) {
        float hv = __ldg(&hr[k]);
        a0 = fmaf(hv, __ldg(&Wn2[k]),       a0);
        a1 = fmaf(hv, __ldg(&Wn2[256 + k]), a1);
        a2 = fmaf(hv, __ldg(&Wn2[512 + k]), a2);
        a3 = fmaf(hv, __ldg(&Wn2[768 + k]), a3);
    }
#pragma unroll
    for (int o = 16; o > 0; o >>= 1) {
        a0 += __shfl_xor_sync(0xffffffff, a0, o);
        a1 += __shfl_xor_sync(0xffffffff, a1, o);
        a2 += __shfl_xor_sync(0xffffffff, a2, o);
        a3 += __shfl_xor_sync(0xffffffff, a3, o);
    }
    if (lane == 0) {
        mod[(size_t)warp * 4 + 0] = 0.5f + sigmoidf_(a0 + bn2[0]);
        mod[(size_t)warp * 4 + 1] = 0.5f + sigmoidf_(a1 + bn2[1]);
        mod[(size_t)warp * 4 + 2] = 0.5f + sigmoidf_(a2 + bn2[2]);
        mod[(size_t)warp * 4 + 3] = 0.5f + sigmoidf_(a3 + bn2[3]);
    }
}

// ---------------- in-place LayerNorm over E per row --------------------------
__global__ void ln_kernel(float* __restrict__ out,
                          const float* __restrict__ gamma,
                          const float* __restrict__ beta) {
    int row = blockIdx.x;
    float* p = out + (size_t)row * E_;
    int tid = threadIdx.x;
    float v[4];
    float s = 0.f, ss = 0.f;
#pragma unroll
    for (int i = 0; i < 4; i++) {
        v[i] = p[tid + i * 256];
        s += v[i];
        ss += v[i] * v[i];
    }
#pragma unroll
    for (int o = 16; o > 0; o >>= 1) {
        s  += __shfl_down_sync(0xffffffff, s,  o);
        ss += __shfl_down_sync(0xffffffff, ss, o);
    }
    __shared__ float shs[8], shss[8];
    __shared__ float mu_s, inv_s;
    int wid = tid >> 5, lane = tid & 31;
    if (lane == 0) { shs[wid] = s; shss[wid] = ss; }
    __syncthreads();
    if (tid == 0) {
        float S = 0.f, SS = 0.f;
#pragma unroll
        for (int w = 0; w < 8; w++) { S += shs[w]; SS += shss[w]; }
        float mu  = S / (float)E_;
        float var = SS / (float)E_ - mu * mu;
        mu_s = mu;
        inv_s = rsqrtf(var + 1e-5f);
    }
    __syncthreads();
    float mu = mu_s, iv = inv_s;
#pragma unroll
    for (int i = 0; i < 4; i++) {
        int c = tid + i * 256;
        p[c] = (v[i] - mu) * iv * __ldg(&gamma[c]) + __ldg(&beta[c]);
    }
}

// ---------------- launch -----------------------------------------------------
extern "C" void kernel_launch(void* const* d_in, const int* in_sizes, int n_in,
                              void* d_out, int out_size) {
    const float* x        = (const float*)d_in[0];
    const float* tau_ctx  = (const float*)d_in[1];
    const float* tau_raws = (const float*)d_in[2];
    const float* Wg       = (const float*)d_in[3];
    const float* bg       = (const float*)d_in[4];
    const float* Wn1      = (const float*)d_in[5];
    const float* bn1      = (const float*)d_in[6];
    const float* Wn2      = (const float*)d_in[7];
    const float* bn2      = (const float*)d_in[8];
    const float* blend    = (const float*)d_in[9];
    const float* Wsoma    = (const float*)d_in[10];
    const float* bsoma    = (const float*)d_in[11];
    const float* Wtemp    = (const float*)d_in[12];
    const float* btemp    = (const float*)d_in[13];
    const float* Wout     = (const float*)d_in[14];
    const float* gamma    = (const float*)d_in[15];
    const float* beta     = (const float*)d_in[16];
    float* out = (float*)d_out;

    float *ctx, *gated, *temporal, *gate, *sg, *h1, *mod, *seg, *seg4;
    float *xr, *wgr, *wn1r, *wtr, *wsr, *wor;
    cudaGetSymbolAddress((void**)&ctx,      g_ctx);
    cudaGetSymbolAddress((void**)&gated,    g_gated);
    cudaGetSymbolAddress((void**)&temporal, g_temporal);
    cudaGetSymbolAddress((void**)&gate,     g_gate);
    cudaGetSymbolAddress((void**)&sg,       g_sg);
    cudaGetSymbolAddress((void**)&h1,       g_h1);
    cudaGetSymbolAddress((void**)&mod,      g_mod);
    cudaGetSymbolAddress((void**)&seg,      g_seg);
    cudaGetSymbolAddress((void**)&seg4,     g_seg4);
    cudaGetSymbolAddress((void**)&xr,       g_xr);
    cudaGetSymbolAddress((void**)&wgr,      g_wgr);
    cudaGetSymbolAddress((void**)&wn1r,     g_wn1r);
    cudaGetSymbolAddress((void**)&wtr,      g_wtr);
    cudaGetSymbolAddress((void**)&wsr,      g_wsr);
    cudaGetSymbolAddress((void**)&wor,      g_wor);

    cudaFuncSetAttribute(gemm_mma, cudaFuncAttributeMaxDynamicSharedMemorySize, DYN_SMEM);
    cudaFuncSetAttribute(gemm_mma, cudaFuncAttributePreferredSharedMemoryCarveout,
                         cudaSharedmemCarveoutMaxShared);

    // one-time stream/event setup (happens on the first, uncaptured call;
    // capture replays only the recorded fork/join edges)
    static cudaStream_t s1 = nullptr;
    static cudaEvent_t evA = nullptr, evB = nullptr;
    if (s1 == nullptr) {
        cudaStreamCreateWithFlags(&s1, cudaStreamNonBlocking);
        cudaEventCreateWithFlags(&evA, cudaEventDisableTiming);
        cudaEventCreateWithFlags(&evB, cudaEventDisableTiming);
    }

    const int NSEG_T = B_ * E_ * SEG_;
    dim3 gridE(E_ / 128, BT_ / 128);       // 8 x 64
    dim3 gridH(256 / 128, BT_ / 128);      // 2 x 64

    // ---- s0: produce xr (and ctx segment sums) ----
    ema_ctx_p1_roundx<<<NSEG_T / 256, 256>>>(x, tau_ctx, seg, xr);
    cudaEventRecord(evA, 0);

    // ---- s1 (forked): round Wn1/Wsoma, h1 GEMM, soma GEMM, mod ----
    cudaStreamWaitEvent(s1, evA, 0);
    round_w2<<<512, 256, 0, s1>>>(Wn1, Wsoma, wn1r, wsr);
    gemm_mma<<<gridH, 256, DYN_SMEM, s1>>>(xr, nullptr, E_, wn1r, bn1, nullptr,
                                           h1, 256, E_, 2);
    gemm_mma<<<gridE, 256, DYN_SMEM, s1>>>(xr, nullptr, E_, wsr, bsoma, nullptr,
                                           sg, E_, E_, 2);          // soma_raw
    mod_kernel<<<(BT_ * 32) / 256, 256, 0, s1>>>(h1, Wn2, bn2, mod);
    cudaEventRecord(evB, s1);

    // ---- s0: ctx chain + Wg GEMM (overlaps s1) ----
    ema_ctx_p2_roundw<<<1024, 256>>>(tau_ctx, seg, Wg, Wtemp, Wout, wgr, wtr, wor);
    ema_ctx_p3<<<NSEG_T / 256, 256>>>(x, tau_ctx, seg, ctx);
    gemm_mma<<<gridE, 256, DYN_SMEM>>>(xr, ctx, E_, wgr, bg, x, gated, E_, 2 * E_, 1);

    // ---- join: need mod (and later sg) from s1 ----
    cudaStreamWaitEvent(0, evB, 0);

    // ---- trace EMA chain ----
    ema_tr_p1<<<NSEG_T / 256, 256>>>(gated, mod, tau_raws, seg4);
    ema_tr_p2<<<(B_ * E_) / 256, 256>>>(tau_raws, seg4);
    ema_tr_p3<<<NSEG_T / 256, 256>>>(gated, mod, tau_raws, blend, seg4, temporal);

    // ---- gate GEMM with fused soma multiply:
    //      g_gate = tf32f( sigmoid(temporal@Wt + bt) * soma_raw ) ----
    gemm_mma<<<gridE, 256, DYN_SMEM>>>(temporal, nullptr, E_, wtr, btemp, sg,
                                       gate, E_, E_, 5);

    // ---- out = (soma*gate) @ Wout^T ----
    gemm_mma<<<gridE, 256, DYN_SMEM>>>(gate, nullptr, E_, wor, nullptr, nullptr,
                                       out, E_, E_, 0);

    // ---- LayerNorm in place ----
    ln_kernel<<<BT_, 256>>>(out, gamma, beta);
}

// round 13
// speedup vs baseline: 1.1641x; 1.0567x over previous
#include <cuda_runtime.h>
#include <math.h>
#include <cstdint>

#define B_ 4
#define T_ 2048
#define E_ 1024
#define BT_ (B_*T_)
#define SEG_ 16
#define SEGL_ (T_/SEG_)   // 128

// ---------------- scratch (device globals; no allocation allowed) ----------
__device__ float g_ctx[BT_*E_];
__device__ float g_gated[BT_*E_];
__device__ float g_temporal[BT_*E_];
__device__ float g_gate[BT_*E_];
__device__ float g_sg[BT_*E_];
__device__ float g_h1[BT_*256];
__device__ float g_mod[BT_*4];
__device__ float g_seg[B_*SEG_*E_];
__device__ float g_seg4[4*B_*SEG_*E_];
__device__ float g_xr[BT_*E_];
__device__ float g_wgr[E_*2*E_];
__device__ float g_wn1r[256*E_];
__device__ float g_wtr[E_*E_];
__device__ float g_wsr[E_*E_];
__device__ float g_wor[E_*E_];

// ---------------- helpers --------------------------------------------------
__device__ __forceinline__ float sigmoidf_(float x) { return 1.0f / (1.0f + expf(-x)); }
__device__ __forceinline__ float geluf_(float x) {
    return 0.5f * x * (1.0f + erff(x * 0.70710678118654752440f));
}
__device__ __forceinline__ uint32_t to_tf32(float x) {
    uint32_t r;
    asm("cvt.rna.tf32.f32 %0, %1;" : "=r"(r) : "f"(x));
    return r;
}
__device__ __forceinline__ float tf32f(float x) { return __uint_as_float(to_tf32(x)); }

__device__ __forceinline__ uint32_t smem_u32(const void* p) {
    uint32_t a;
    asm("{ .reg .u64 t; cvta.to.shared.u64 t, %1; cvt.u32.u64 %0, t; }" : "=r"(a) : "l"(p));
    return a;
}

#define LDSM_X4(d, addr) \
    asm volatile("ldmatrix.sync.aligned.m8n8.x4.shared.b16 {%0,%1,%2,%3}, [%4];" \
                 : "=r"((d)[0]), "=r"((d)[1]), "=r"((d)[2]), "=r"((d)[3]) : "r"(addr))

#define CP_ASYNC16(dst, src) \
    asm volatile("cp.async.cg.shared.global [%0], [%1], 16;" :: "r"(dst), "l"(src))

// ============================================================================
// s0 Launch 1: ema_ctx_p1 fused with round_x
// ============================================================================
__global__ void ema_ctx_p1_roundx(const float* __restrict__ x,
                                  const float* __restrict__ tau_ctx,
                                  float* __restrict__ seg,
                                  float* __restrict__ xr) {
    int tid = blockIdx.x * blockDim.x + threadIdx.x;
    if (tid >= B_ * E_ * SEG_) return;
    int e = tid & (E_ - 1);
    int s = (tid >> 10) & (SEG_ - 1);
    int b = tid >> 14;
    float alpha = 1.0f / (1.0f + expf(tau_ctx[0]));
    size_t base = ((size_t)(b * T_ + s * SEGL_)) * E_ + e;
    float h = 0.0f;
    for (int t = 0; t < SEGL_; t += 8) {
        float v[8];
#pragma unroll
        for (int i = 0; i < 8; i++) v[i] = __ldg(&x[base + (size_t)(t + i) * E_]);
#pragma unroll
        for (int i = 0; i < 8; i++) {
            h = fmaf(alpha, h, v[i]);
            xr[base + (size_t)(t + i) * E_] = tf32f(v[i]);
        }
    }
    seg[(b * SEG_ + s) * E_ + e] = h;
}

// ============================================================================
// s1: round Wn1 + Wsoma
// ============================================================================
__global__ void round_w2(const float* __restrict__ Wn1, const float* __restrict__ Ws,
                         float* __restrict__ wn1r, float* __restrict__ wsr) {
    const int n_wn1 = 256 * E_ / 4;
    const int n_w   = E_ * E_ / 4;
    const int total = n_wn1 + n_w;
    int i = blockIdx.x * blockDim.x + threadIdx.x;
    int stride = gridDim.x * blockDim.x;
    for (; i < total; i += stride) {
        const float* src; float* dst; int j = i;
        if (j < n_wn1) { src = Wn1; dst = wn1r; }
        else { j -= n_wn1; src = Ws; dst = wsr; }
        float4 v = reinterpret_cast<const float4*>(src)[j];
        v.x = tf32f(v.x); v.y = tf32f(v.y); v.z = tf32f(v.z); v.w = tf32f(v.w);
        reinterpret_cast<float4*>(dst)[j] = v;
    }
}

// ============================================================================
// s0: ema_ctx_p2 carry scan fused with rounding Wg/Wtemp/Wout
// ============================================================================
__global__ void ema_ctx_p2_roundw(const float* __restrict__ tau_ctx,
                                  float* __restrict__ seg,
                                  const float* __restrict__ Wg,
                                  const float* __restrict__ Wt,
                                  const float* __restrict__ Wo,
                                  float* __restrict__ wgr,
                                  float* __restrict__ wtr,
                                  float* __restrict__ wor) {
    int tid = blockIdx.x * blockDim.x + threadIdx.x;
    if (tid < B_ * E_) {
        int e = tid & (E_ - 1);
        int b = tid >> 10;
        float alpha = 1.0f / (1.0f + expf(tau_ctx[0]));
        float aL = 1.0f;
        for (int k = 0; k < SEGL_; k++) aL *= alpha;
        float carry = 0.0f;
        for (int s = 0; s < SEG_; s++) {
            size_t idx = (size_t)(b * SEG_ + s) * E_ + e;
            float Es = seg[idx];
            seg[idx] = carry;
            carry = fmaf(aL, carry, Es);
        }
    }
    const int n_wg = E_ * 2 * E_ / 4;
    const int n_w  = E_ * E_ / 4;
    const int total = n_wg + 2 * n_w;
    int stride = gridDim.x * blockDim.x;
    for (int i = tid; i < total; i += stride) {
        const float* src; float* dst; int j = i;
        if (j < n_wg) { src = Wg; dst = wgr; }
        else {
            j -= n_wg;
            if (j < n_w) { src = Wt; dst = wtr; }
            else { j -= n_w; src = Wo; dst = wor; }
        }
        float4 v = reinterpret_cast<const float4*>(src)[j];
        v.x = tf32f(v.x); v.y = tf32f(v.y); v.z = tf32f(v.z); v.w = tf32f(v.w);
        reinterpret_cast<float4*>(dst)[j] = v;
    }
}

// ============================================================================
// ema_ctx_p3 — replay with carry, store tf32-rounded ctx
// ============================================================================
__global__ void ema_ctx_p3(const float* __restrict__ x,
                           const float* __restrict__ tau_ctx,
                           const float* __restrict__ seg,
                           float* __restrict__ ctx) {
    int tid = blockIdx.x * blockDim.x + threadIdx.x;
    if (tid >= B_ * E_ * SEG_) return;
    int e = tid & (E_ - 1);
    int s = (tid >> 10) & (SEG_ - 1);
    int b = tid >> 14;
    float alpha = 1.0f / (1.0f + expf(tau_ctx[0]));
    size_t base = ((size_t)(b * T_ + s * SEGL_)) * E_ + e;
    float h = seg[(b * SEG_ + s) * E_ + e];
    for (int t = 0; t < SEGL_; t += 8) {
        float v[8];
#pragma unroll
        for (int i = 0; i < 8; i++) v[i] = __ldg(&x[base + (size_t)(t + i) * E_]);
#pragma unroll
        for (int i = 0; i < 8; i++) {
            h = fmaf(alpha, h, v[i]);
            ctx[base + (size_t)(t + i) * E_] = tf32f(h);
        }
    }
}

// ============================================================================
// Segmented EMA for the 4 modulated traces + blend — HALF-BATCH versions
// (b0 = first batch of the half; covers 2 batches)
// ============================================================================
__global__ void ema_tr_p1(const float* __restrict__ gated,
                          const float* __restrict__ mod,
                          const float* __restrict__ tau_raws,
                          float* __restrict__ seg4, int b0) {
    int tid = blockIdx.x * blockDim.x + threadIdx.x;
    if (tid >= (B_/2) * E_ * SEG_) return;
    int e = tid & (E_ - 1);
    int s = (tid >> 10) & (SEG_ - 1);
    int b = b0 + (tid >> 14);
    float al[4];
#pragma unroll
    for (int d = 0; d < 4; d++) al[d] = 1.0f / (1.0f + expf(tau_raws[d]));
    size_t base = ((size_t)(b * T_ + s * SEGL_)) * E_ + e;
    const float4* mod4 = reinterpret_cast<const float4*>(mod);
    size_t mbase = (size_t)b * T_ + s * SEGL_;
    float h0 = 0.f, h1 = 0.f, h2 = 0.f, h3 = 0.f;
    for (int t = 0; t < SEGL_; t += 4) {
        float g[4]; float4 mm[4];
#pragma unroll
        for (int i = 0; i < 4; i++) {
            g[i]  = __ldg(&gated[base + (size_t)(t + i) * E_]);
            mm[i] = __ldg(&mod4[mbase + t + i]);
        }
#pragma unroll
        for (int i = 0; i < 4; i++) {
            h0 = fmaf(al[0], h0, g[i] * mm[i].x);
            h1 = fmaf(al[1], h1, g[i] * mm[i].y);
            h2 = fmaf(al[2], h2, g[i] * mm[i].z);
            h3 = fmaf(al[3], h3, g[i] * mm[i].w);
        }
    }
    size_t o = (size_t)(b * SEG_ + s) * E_ + e;
    seg4[0 * (B_*SEG_*E_) + o] = h0;
    seg4[1 * (B_*SEG_*E_) + o] = h1;
    seg4[2 * (B_*SEG_*E_) + o] = h2;
    seg4[3 * (B_*SEG_*E_) + o] = h3;
}

__global__ void ema_tr_p2(const float* __restrict__ tau_raws,
                          float* __restrict__ seg4, int b0) {
    int tid = blockIdx.x * blockDim.x + threadIdx.x;
    if (tid >= (B_/2) * E_) return;
    int e = tid & (E_ - 1);
    int b = b0 + (tid >> 10);
#pragma unroll
    for (int d = 0; d < 4; d++) {
        float alpha = 1.0f / (1.0f + expf(tau_raws[d]));
        float aL = 1.0f;
        for (int k = 0; k < SEGL_; k++) aL *= alpha;
        float carry = 0.0f;
        for (int s = 0; s < SEG_; s++) {
            size_t idx = (size_t)d * (B_*SEG_*E_) + (size_t)(b * SEG_ + s) * E_ + e;
            float Es = seg4[idx];
            seg4[idx] = carry;
            carry = fmaf(aL, carry, Es);
        }
    }
}

__global__ void ema_tr_p3(const float* __restrict__ gated,
                          const float* __restrict__ mod,
                          const float* __restrict__ tau_raws,
                          const float* __restrict__ blend,
                          const float* __restrict__ seg4,
                          float* __restrict__ temporal, int b0) {
    int tid = blockIdx.x * blockDim.x + threadIdx.x;
    if (tid >= (B_/2) * E_ * SEG_) return;
    int e = tid & (E_ - 1);
    int s = (tid >> 10) & (SEG_ - 1);
    int b = b0 + (tid >> 14);

    float al[4];
#pragma unroll
    for (int d = 0; d < 4; d++) al[d] = 1.0f / (1.0f + expf(tau_raws[d]));

    float bl[4];
#pragma unroll
    for (int d = 0; d < 4; d++) bl[d] = blend[d * E_ + e];
    float mx = fmaxf(fmaxf(bl[0], bl[1]), fmaxf(bl[2], bl[3]));
    float bw[4], sum = 0.0f;
#pragma unroll
    for (int d = 0; d < 4; d++) { bw[d] = expf(bl[d] - mx); sum += bw[d]; }
    float inv = 1.0f / sum;
#pragma unroll
    for (int d = 0; d < 4; d++) bw[d] *= inv;

    size_t base = ((size_t)(b * T_ + s * SEGL_)) * E_ + e;
    const float4* mod4 = reinterpret_cast<const float4*>(mod);
    size_t mbase = (size_t)b * T_ + s * SEGL_;
    size_t o = (size_t)(b * SEG_ + s) * E_ + e;
    float h0 = seg4[0 * (B_*SEG_*E_) + o];
    float h1 = seg4[1 * (B_*SEG_*E_) + o];
    float h2 = seg4[2 * (B_*SEG_*E_) + o];
    float h3 = seg4[3 * (B_*SEG_*E_) + o];

    for (int t = 0; t < SEGL_; t += 4) {
        float g[4]; float4 mm[4];
#pragma unroll
        for (int i = 0; i < 4; i++) {
            g[i]  = __ldg(&gated[base + (size_t)(t + i) * E_]);
            mm[i] = __ldg(&mod4[mbase + t + i]);
        }
#pragma unroll
        for (int i = 0; i < 4; i++) {
            h0 = fmaf(al[0], h0, g[i] * mm[i].x);
            h1 = fmaf(al[1], h1, g[i] * mm[i].y);
            h2 = fmaf(al[2], h2, g[i] * mm[i].z);
            h3 = fmaf(al[3], h3, g[i] * mm[i].w);
            temporal[base + (size_t)(t + i) * E_] =
                tf32f(bw[0] * h0 + bw[1] * h1 + bw[2] * h2 + bw[3] * h3);
        }
    }
}

// ============================================================================
// tf32 mma.sync GEMM (R10 shape — unchanged)
// mode: 0 none, 1 sigmoid(.)*extra, 2 gelu, 3 sigmoid,
//       5 tf32f(sigmoid(.)*extra)
// ============================================================================
static constexpr int STAGE_BYTES = 32768;
static constexpr int NSTAGE = 3;
static constexpr int LDC = 132;
static constexpr int DYN_SMEM = NSTAGE * STAGE_BYTES;  // 98304

__global__ void __launch_bounds__(256, 2)
gemm_mma(const float* __restrict__ A, const float* __restrict__ A2, int KA,
         const float* __restrict__ W, const float* __restrict__ bias,
         const float* __restrict__ extra, float* __restrict__ C,
         int N, int K, int mode) {
    extern __shared__ float smem[];
    uint32_t sb = smem_u32(smem);
    int tid = threadIdx.x, wid = tid >> 5, lane = tid & 31;
    int bm = blockIdx.y * 128, bn = blockIdx.x * 128;
    int wm = wid & 1;
    int wn = wid >> 1;

    float acc[4][4][4];
#pragma unroll
    for (int i = 0; i < 4; i++)
#pragma unroll
        for (int j = 0; j < 4; j++)
#pragma unroll
            for (int r = 0; r < 4; r++) acc[i][j][r] = 0.0f;

    const int NC = K / 32;

    int p7 = lane & 7;
    uint32_t aRow[4], bRow[2];
#pragma unroll
    for (int i = 0; i < 4; i++)
        aRow[i] = (uint32_t)(wm * 64 + i * 16 + p7 + 8 * ((lane >> 3) & 1)) * 128u;
#pragma unroll
    for (int j2 = 0; j2 < 2; j2++)
        bRow[j2] = (uint32_t)(wn * 32 + j2 * 16 + p7 + 8 * (lane >> 4)) * 128u;
    uint32_t swzA[4], swzB[4];
#pragma unroll
    for (int ks = 0; ks < 4; ks++) {
        swzA[ks] = (uint32_t)(((ks * 2 + (lane >> 4)) ^ p7) * 16);
        swzB[ks] = (uint32_t)(((ks * 2 + ((lane >> 3) & 1)) ^ p7) * 16);
    }

    auto load_chunk = [&](int c, int s) {
        int k0 = c * 32;
        const float* srcA = A; int ka = k0;
        if (A2 != nullptr && k0 >= KA) { srcA = A2; ka = k0 - KA; }
        uint32_t dstA = sb + (uint32_t)s * STAGE_BYTES;
        uint32_t dstB = dstA + 16384;
#pragma unroll
        for (int q = 0; q < 4; q++) {
            int idx = tid + q * 256;
            int row = idx >> 3, ch = idx & 7;
            uint32_t off = (uint32_t)row * 128u + (uint32_t)((ch ^ (row & 7)) * 16);
            const float* sA = srcA + (size_t)(bm + row) * KA + ka + ch * 4;
            CP_ASYNC16(dstA + off, sA);
            const float* sB = W + (size_t)(bn + row) * K + k0 + ch * 4;
            CP_ASYNC16(dstB + off, sB);
        }
        asm volatile("cp.async.commit_group;" ::: "memory");
    };

    load_chunk(0, 0);
    load_chunk(1, 1);

    for (int c = 0; c < NC; c++) {
        int s = c % NSTAGE;
        if (c < NC - 1) asm volatile("cp.async.wait_group 1;" ::: "memory");
        else            asm volatile("cp.async.wait_group 0;" ::: "memory");
        __syncthreads();
        if (c + 2 < NC) load_chunk(c + 2, (c + 2) % NSTAGE);

        uint32_t baseA = sb + (uint32_t)s * STAGE_BYTES;
        uint32_t baseB = baseA + 16384;
#pragma unroll
        for (int ks = 0; ks < 4; ks++) {
            uint32_t a[4][4], b[2][4];
#pragma unroll
            for (int i = 0; i < 4; i++) LDSM_X4(a[i], baseA + aRow[i] + swzA[ks]);
#pragma unroll
            for (int j2 = 0; j2 < 2; j2++) LDSM_X4(b[j2], baseB + bRow[j2] + swzB[ks]);
#pragma unroll
            for (int i = 0; i < 4; i++)
#pragma unroll
                for (int j = 0; j < 4; j++) {
                    asm volatile(
                        "mma.sync.aligned.m16n8k8.row.col.f32.tf32.tf32.f32 "
                        "{%0,%1,%2,%3}, {%4,%5,%6,%7}, {%8,%9}, {%0,%1,%2,%3};"
                        : "+f"(acc[i][j][0]), "+f"(acc[i][j][1]),
                          "+f"(acc[i][j][2]), "+f"(acc[i][j][3])
                        : "r"(a[i][0]), "r"(a[i][1]), "r"(a[i][2]), "r"(a[i][3]),
                          "r"(b[j >> 1][(j & 1) * 2]), "r"(b[j >> 1][(j & 1) * 2 + 1]));
                }
        }
    }
    __syncthreads();

    float* Cs = smem;
#pragma unroll
    for (int i = 0; i < 4; i++)
#pragma unroll
        for (int j = 0; j < 4; j++) {
            int r0 = wm * 64 + i * 16 + (lane >> 2);
            int c0 = wn * 32 + j * 8 + (lane & 3) * 2;
            *reinterpret_cast<float2*>(Cs + r0 * LDC + c0) =
                make_float2(acc[i][j][0], acc[i][j][1]);
            *reinterpret_cast<float2*>(Cs + (r0 + 8) * LDC + c0) =
                make_float2(acc[i][j][2], acc[i][j][3]);
        }
    __syncthreads();

    for (int t = tid; t < 128 * 32; t += 256) {
        int r = t >> 5, c0 = (t & 31) * 4;
        const float* rg = Cs + r * LDC + c0;
        int m = bm + r, n = bn + c0;
        size_t oidx = (size_t)m * N + n;
        float v[4];
#pragma unroll
        for (int i = 0; i < 4; i++) {
            v[i] = rg[i];
            if (bias != nullptr) v[i] += __ldg(&bias[n + i]);
        }
        if (mode == 1 || mode == 5) {
            float4 ex = *reinterpret_cast<const float4*>(extra + oidx);
            float exv[4] = {ex.x, ex.y, ex.z, ex.w};
#pragma unroll
            for (int i = 0; i < 4; i++) {
                float p = sigmoidf_(v[i]) * exv[i];
                v[i] = (mode == 1) ? p : tf32f(p);
            }
        } else if (mode == 2) {
#pragma unroll
            for (int i = 0; i < 4; i++) v[i] = geluf_(v[i]);
        } else if (mode == 3) {
#pragma unroll
            for (int i = 0; i < 4; i++) v[i] = sigmoidf_(v[i]);
        }
        *reinterpret_cast<float4*>(C + oidx) = make_float4(v[0], v[1], v[2], v[3]);
    }
}

// ---------------- mod = 0.5 + sigmoid(h1 @ Wn2^T + bn2) ---------------------
__global__ void mod_kernel(const float* __restrict__ h1,
                           const float* __restrict__ Wn2,
                           const float* __restrict__ bn2,
                           float* __restrict__ mod) {
    int warp = (blockIdx.x * blockDim.x + threadIdx.x) >> 5;
    int lane = threadIdx.x & 31;
    if (warp >= BT_) return;
    const float* hr = h1 + (size_t)warp * 256;
    float a0 = 0.f, a1 = 0.f, a2 = 0.f, a3 = 0.f;
    for (int k = lane; k < 256; k += 32) {
        float hv = __ldg(&hr[k]);
        a0 = fmaf(hv, __ldg(&Wn2[k]),       a0);
        a1 = fmaf(hv, __ldg(&Wn2[256 + k]), a1);
        a2 = fmaf(hv, __ldg(&Wn2[512 + k]), a2);
        a3 = fmaf(hv, __ldg(&Wn2[768 + k]), a3);
    }
#pragma unroll
    for (int o = 16; o > 0; o >>= 1) {
        a0 += __shfl_xor_sync(0xffffffff, a0, o);
        a1 += __shfl_xor_sync(0xffffffff, a1, o);
        a2 += __shfl_xor_sync(0xffffffff, a2, o);
        a3 += __shfl_xor_sync(0xffffffff, a3, o);
    }
    if (lane == 0) {
        mod[(size_t)warp * 4 + 0] = 0.5f + sigmoidf_(a0 + bn2[0]);
        mod[(size_t)warp * 4 + 1] = 0.5f + sigmoidf_(a1 + bn2[1]);
        mod[(size_t)warp * 4 + 2] = 0.5f + sigmoidf_(a2 + bn2[2]);
        mod[(size_t)warp * 4 + 3] = 0.5f + sigmoidf_(a3 + bn2[3]);
    }
}

// ---------------- in-place LayerNorm over E per row --------------------------
__global__ void ln_kernel(float* __restrict__ out,
                          const float* __restrict__ gamma,
                          const float* __restrict__ beta) {
    int row = blockIdx.x;
    float* p = out + (size_t)row * E_;
    int tid = threadIdx.x;
    float v[4];
    float s = 0.f, ss = 0.f;
#pragma unroll
    for (int i = 0; i < 4; i++) {
        v[i] = p[tid + i * 256];
        s += v[i];
        ss += v[i] * v[i];
    }
#pragma unroll
    for (int o = 16; o > 0; o >>= 1) {
        s  += __shfl_down_sync(0xffffffff, s,  o);
        ss += __shfl_down_sync(0xffffffff, ss, o);
    }
    __shared__ float shs[8], shss[8];
    __shared__ float mu_s, inv_s;
    int wid = tid >> 5, lane = tid & 31;
    if (lane == 0) { shs[wid] = s; shss[wid] = ss; }
    __syncthreads();
    if (tid == 0) {
        float S = 0.f, SS = 0.f;
#pragma unroll
        for (int w = 0; w < 8; w++) { S += shs[w]; SS += shss[w]; }
        float mu  = S / (float)E_;
        float var = SS / (float)E_ - mu * mu;
        mu_s = mu;
        inv_s = rsqrtf(var + 1e-5f);
    }
    __syncthreads();
    float mu = mu_s, iv = inv_s;
#pragma unroll
    for (int i = 0; i < 4; i++) {
        int c = tid + i * 256;
        p[c] = (v[i] - mu) * iv * __ldg(&gamma[c]) + __ldg(&beta[c]);
    }
}

// ---------------- launch -----------------------------------------------------
extern "C" void kernel_launch(void* const* d_in, const int* in_sizes, int n_in,
                              void* d_out, int out_size) {
    const float* x        = (const float*)d_in[0];
    const float* tau_ctx  = (const float*)d_in[1];
    const float* tau_raws = (const float*)d_in[2];
    const float* Wg       = (const float*)d_in[3];
    const float* bg       = (const float*)d_in[4];
    const float* Wn1      = (const float*)d_in[5];
    const float* bn1      = (const float*)d_in[6];
    const float* Wn2      = (const float*)d_in[7];
    const float* bn2      = (const float*)d_in[8];
    const float* blend    = (const float*)d_in[9];
    const float* Wsoma    = (const float*)d_in[10];
    const float* bsoma    = (const float*)d_in[11];
    const float* Wtemp    = (const float*)d_in[12];
    const float* btemp    = (const float*)d_in[13];
    const float* Wout     = (const float*)d_in[14];
    const float* gamma    = (const float*)d_in[15];
    const float* beta     = (const float*)d_in[16];
    float* out = (float*)d_out;

    float *ctx, *gated, *temporal, *gate, *sg, *h1, *mod, *seg, *seg4;
    float *xr, *wgr, *wn1r, *wtr, *wsr, *wor;
    cudaGetSymbolAddress((void**)&ctx,      g_ctx);
    cudaGetSymbolAddress((void**)&gated,    g_gated);
    cudaGetSymbolAddress((void**)&temporal, g_temporal);
    cudaGetSymbolAddress((void**)&gate,     g_gate);
    cudaGetSymbolAddress((void**)&sg,       g_sg);
    cudaGetSymbolAddress((void**)&h1,       g_h1);
    cudaGetSymbolAddress((void**)&mod,      g_mod);
    cudaGetSymbolAddress((void**)&seg,      g_seg);
    cudaGetSymbolAddress((void**)&seg4,     g_seg4);
    cudaGetSymbolAddress((void**)&xr,       g_xr);
    cudaGetSymbolAddress((void**)&wgr,      g_wgr);
    cudaGetSymbolAddress((void**)&wn1r,     g_wn1r);
    cudaGetSymbolAddress((void**)&wtr,      g_wtr);
    cudaGetSymbolAddress((void**)&wsr,      g_wsr);
    cudaGetSymbolAddress((void**)&wor,      g_wor);

    cudaFuncSetAttribute(gemm_mma, cudaFuncAttributeMaxDynamicSharedMemorySize, DYN_SMEM);
    cudaFuncSetAttribute(gemm_mma, cudaFuncAttributePreferredSharedMemoryCarveout,
                         cudaSharedmemCarveoutMaxShared);

    static cudaStream_t s1 = nullptr;
    static cudaEvent_t evA = nullptr, evB = nullptr, evG = nullptr, evC = nullptr;
    if (s1 == nullptr) {
        cudaStreamCreateWithFlags(&s1, cudaStreamNonBlocking);
        cudaEventCreateWithFlags(&evA, cudaEventDisableTiming);
        cudaEventCreateWithFlags(&evB, cudaEventDisableTiming);
        cudaEventCreateWithFlags(&evG, cudaEventDisableTiming);
        cudaEventCreateWithFlags(&evC, cudaEventDisableTiming);
    }

    const int NSEG_T = B_ * E_ * SEG_;      // 65536
    const int NSEG_H = NSEG_T / 2;          // 32768 (half-batch)
    const size_t HOFF = (size_t)(BT_ / 2) * E_;   // element offset of batch half 1
    dim3 gridE(E_ / 128, BT_ / 128);        // 8 x 64 (full)
    dim3 gridEH(E_ / 128, BT_ / 256);       // 8 x 32 (half)
    dim3 gridH(256 / 128, BT_ / 128);       // 2 x 64

    // ---- s0: produce xr + ctx segment sums ----
    ema_ctx_p1_roundx<<<NSEG_T / 256, 256>>>(x, tau_ctx, seg, xr);
    cudaEventRecord(evA, 0);

    // ---- s1 (forked): round Wn1/Wsoma, h1 GEMM, soma GEMM, mod ----
    cudaStreamWaitEvent(s1, evA, 0);
    round_w2<<<512, 256, 0, s1>>>(Wn1, Wsoma, wn1r, wsr);
    gemm_mma<<<gridH, 256, DYN_SMEM, s1>>>(xr, nullptr, E_, wn1r, bn1, nullptr,
                                           h1, 256, E_, 2);
    gemm_mma<<<gridE, 256, DYN_SMEM, s1>>>(xr, nullptr, E_, wsr, bsoma, nullptr,
                                           sg, E_, E_, 2);          // soma_raw
    mod_kernel<<<(BT_ * 32) / 256, 256, 0, s1>>>(h1, Wn2, bn2, mod);
    cudaEventRecord(evB, s1);

    // ---- s0: ctx chain + Wg GEMM (overlaps s1) ----
    ema_ctx_p2_roundw<<<1024, 256>>>(tau_ctx, seg, Wg, Wtemp, Wout, wgr, wtr, wor);
    ema_ctx_p3<<<NSEG_T / 256, 256>>>(x, tau_ctx, seg, ctx);
    gemm_mma<<<gridE, 256, DYN_SMEM>>>(xr, ctx, E_, wgr, bg, x, gated, E_, 2 * E_, 1);
    cudaEventRecord(evG, 0);

    // ================= batch-split pipelined tail =================
    // s0 handles batches {0,1}; s1 handles batches {2,3}.
    // s0 needs mod/sg from s1 (evB); s1 needs gated/wtr/wor from s0 (evG).
    cudaStreamWaitEvent(0, evB, 0);
    cudaStreamWaitEvent(s1, evG, 0);

    // ---- s0 half 0 ----
    ema_tr_p1<<<NSEG_H / 256, 256>>>(gated, mod, tau_raws, seg4, 0);
    ema_tr_p2<<<(B_/2 * E_) / 256, 256>>>(tau_raws, seg4, 0);
    ema_tr_p3<<<NSEG_H / 256, 256>>>(gated, mod, tau_raws, blend, seg4, temporal, 0);
    gemm_mma<<<gridEH, 256, DYN_SMEM>>>(temporal, nullptr, E_, wtr, btemp, sg,
                                        gate, E_, E_, 5);
    gemm_mma<<<gridEH, 256, DYN_SMEM>>>(gate, nullptr, E_, wor, nullptr, nullptr,
                                        out, E_, E_, 0);

    // ---- s1 half 1 ----
    ema_tr_p1<<<NSEG_H / 256, 256, 0, s1>>>(gated, mod, tau_raws, seg4, 2);
    ema_tr_p2<<<(B_/2 * E_) / 256, 256, 0, s1>>>(tau_raws, seg4, 2);
    ema_tr_p3<<<NSEG_H / 256, 256, 0, s1>>>(gated, mod, tau_raws, blend, seg4,
                                            temporal, 2);
    gemm_mma<<<gridEH, 256, DYN_SMEM, s1>>>(temporal + HOFF, nullptr, E_, wtr, btemp,
                                            sg + HOFF, gate + HOFF, E_, E_, 5);
    gemm_mma<<<gridEH, 256, DYN_SMEM, s1>>>(gate + HOFF, nullptr, E_, wor, nullptr,
                                            nullptr, out + HOFF, E_, E_, 0);
    cudaEventRecord(evC, s1);

    // ---- join + LayerNorm (whole) ----
    cudaStreamWaitEvent(0, evC, 0);
    ln_kernel<<<BT_, 256>>>(out, gamma, beta);
}

// round 14
// speedup vs baseline: 1.2849x; 1.1039x over previous
#include <cuda_runtime.h>
#include <math.h>
#include <cstdint>

#define B_ 4
#define T_ 2048
#define E_ 1024
#define BT_ (B_*T_)
#define SEG_ 32
#define SEGL_ (T_/SEG_)   // 64

// ---------------- scratch (device globals; no allocation allowed) ----------
__device__ float g_ctx[BT_*E_];
__device__ float g_gated[BT_*E_];
__device__ float g_temporal[BT_*E_];
__device__ float g_gate[BT_*E_];
__device__ float g_sg[BT_*E_];
__device__ float g_h1[BT_*256];
__device__ float g_mod[BT_*4];
__device__ float g_seg[B_*SEG_*E_];
__device__ float g_seg4[4*B_*SEG_*E_];
__device__ float g_xr[BT_*E_];
__device__ float g_wgr[E_*2*E_];
__device__ float g_wn1r[256*E_];
__device__ float g_wtr[E_*E_];
__device__ float g_wsr[E_*E_];
__device__ float g_wor[E_*E_];

// ---------------- helpers --------------------------------------------------
__device__ __forceinline__ float sigmoidf_(float x) { return 1.0f / (1.0f + expf(-x)); }
__device__ __forceinline__ float geluf_(float x) {
    return 0.5f * x * (1.0f + erff(x * 0.70710678118654752440f));
}
__device__ __forceinline__ uint32_t to_tf32(float x) {
    uint32_t r;
    asm("cvt.rna.tf32.f32 %0, %1;" : "=r"(r) : "f"(x));
    return r;
}
__device__ __forceinline__ float tf32f(float x) { return __uint_as_float(to_tf32(x)); }

__device__ __forceinline__ uint32_t smem_u32(const void* p) {
    uint32_t a;
    asm("{ .reg .u64 t; cvta.to.shared.u64 t, %1; cvt.u32.u64 %0, t; }" : "=r"(a) : "l"(p));
    return a;
}

#define LDSM_X4(d, addr) \
    asm volatile("ldmatrix.sync.aligned.m8n8.x4.shared.b16 {%0,%1,%2,%3}, [%4];" \
                 : "=r"((d)[0]), "=r"((d)[1]), "=r"((d)[2]), "=r"((d)[3]) : "r"(addr))

#define CP_ASYNC16(dst, src) \
    asm volatile("cp.async.cg.shared.global [%0], [%1], 16;" :: "r"(dst), "l"(src))

// ============================================================================
// s0 Launch: ema_ctx_p1 fused with round_x  (SEG=32 -> 131072 threads)
// ============================================================================
__global__ void ema_ctx_p1_roundx(const float* __restrict__ x,
                                  const float* __restrict__ tau_ctx,
                                  float* __restrict__ seg,
                                  float* __restrict__ xr) {
    int tid = blockIdx.x * blockDim.x + threadIdx.x;
    if (tid >= B_ * E_ * SEG_) return;
    int e = tid & (E_ - 1);
    int s = (tid >> 10) & (SEG_ - 1);
    int b = tid >> 15;
    float alpha = 1.0f / (1.0f + expf(tau_ctx[0]));
    size_t base = ((size_t)(b * T_ + s * SEGL_)) * E_ + e;
    float h = 0.0f;
    for (int t = 0; t < SEGL_; t += 8) {
        float v[8];
#pragma unroll
        for (int i = 0; i < 8; i++) v[i] = __ldg(&x[base + (size_t)(t + i) * E_]);
#pragma unroll
        for (int i = 0; i < 8; i++) {
            h = fmaf(alpha, h, v[i]);
            xr[base + (size_t)(t + i) * E_] = tf32f(v[i]);
        }
    }
    seg[(b * SEG_ + s) * E_ + e] = h;
}

// ============================================================================
// s1 Launch (t=0, no deps): round Wn1 + Wsoma
// ============================================================================
__global__ void round_w2(const float* __restrict__ Wn1, const float* __restrict__ Ws,
                         float* __restrict__ wn1r, float* __restrict__ wsr) {
    const int n_wn1 = 256 * E_ / 4;
    const int n_w   = E_ * E_ / 4;
    const int total = n_wn1 + n_w;
    int i = blockIdx.x * blockDim.x + threadIdx.x;
    int stride = gridDim.x * blockDim.x;
    for (; i < total; i += stride) {
        const float* src; float* dst; int j = i;
        if (j < n_wn1) { src = Wn1; dst = wn1r; }
        else { j -= n_wn1; src = Ws; dst = wsr; }
        float4 v = reinterpret_cast<const float4*>(src)[j];
        v.x = tf32f(v.x); v.y = tf32f(v.y); v.z = tf32f(v.z); v.w = tf32f(v.w);
        reinterpret_cast<float4*>(dst)[j] = v;
    }
}

// ============================================================================
// s0: ema_ctx_p2 carry scan fused with rounding Wg/Wtemp/Wout
// ============================================================================
__global__ void ema_ctx_p2_roundw(const float* __restrict__ tau_ctx,
                                  float* __restrict__ seg,
                                  const float* __restrict__ Wg,
                                  const float* __restrict__ Wt,
                                  const float* __restrict__ Wo,
                                  float* __restrict__ wgr,
                                  float* __restrict__ wtr,
                                  float* __restrict__ wor) {
    int tid = blockIdx.x * blockDim.x + threadIdx.x;
    if (tid < B_ * E_) {
        int e = tid & (E_ - 1);
        int b = tid >> 10;
        float alpha = 1.0f / (1.0f + expf(tau_ctx[0]));
        float aL = 1.0f;
        for (int k = 0; k < SEGL_; k++) aL *= alpha;
        float carry = 0.0f;
        for (int s = 0; s < SEG_; s++) {
            size_t idx = (size_t)(b * SEG_ + s) * E_ + e;
            float Es = seg[idx];
            seg[idx] = carry;
            carry = fmaf(aL, carry, Es);
        }
    }
    const int n_wg = E_ * 2 * E_ / 4;
    const int n_w  = E_ * E_ / 4;
    const int total = n_wg + 2 * n_w;
    int stride = gridDim.x * blockDim.x;
    for (int i = tid; i < total; i += stride) {
        const float* src; float* dst; int j = i;
        if (j < n_wg) { src = Wg; dst = wgr; }
        else {
            j -= n_wg;
            if (j < n_w) { src = Wt; dst = wtr; }
            else { j -= n_w; src = Wo; dst = wor; }
        }
        float4 v = reinterpret_cast<const float4*>(src)[j];
        v.x = tf32f(v.x); v.y = tf32f(v.y); v.z = tf32f(v.z); v.w = tf32f(v.w);
        reinterpret_cast<float4*>(dst)[j] = v;
    }
}

// ============================================================================
// ema_ctx_p3 — replay with carry, store tf32-rounded ctx
// ============================================================================
__global__ void ema_ctx_p3(const float* __restrict__ x,
                           const float* __restrict__ tau_ctx,
                           const float* __restrict__ seg,
                           float* __restrict__ ctx) {
    int tid = blockIdx.x * blockDim.x + threadIdx.x;
    if (tid >= B_ * E_ * SEG_) return;
    int e = tid & (E_ - 1);
    int s = (tid >> 10) & (SEG_ - 1);
    int b = tid >> 15;
    float alpha = 1.0f / (1.0f + expf(tau_ctx[0]));
    size_t base = ((size_t)(b * T_ + s * SEGL_)) * E_ + e;
    float h = seg[(b * SEG_ + s) * E_ + e];
    for (int t = 0; t < SEGL_; t += 8) {
        float v[8];
#pragma unroll
        for (int i = 0; i < 8; i++) v[i] = __ldg(&x[base + (size_t)(t + i) * E_]);
#pragma unroll
        for (int i = 0; i < 8; i++) {
            h = fmaf(alpha, h, v[i]);
            ctx[base + (size_t)(t + i) * E_] = tf32f(h);
        }
    }
}

// ============================================================================
// Segmented EMA for the 4 modulated traces + blend — HALF-BATCH versions
// ============================================================================
__global__ void ema_tr_p1(const float* __restrict__ gated,
                          const float* __restrict__ mod,
                          const float* __restrict__ tau_raws,
                          float* __restrict__ seg4, int b0) {
    int tid = blockIdx.x * blockDim.x + threadIdx.x;
    if (tid >= (B_/2) * E_ * SEG_) return;
    int e = tid & (E_ - 1);
    int s = (tid >> 10) & (SEG_ - 1);
    int b = b0 + (tid >> 15);
    float al[4];
#pragma unroll
    for (int d = 0; d < 4; d++) al[d] = 1.0f / (1.0f + expf(tau_raws[d]));
    size_t base = ((size_t)(b * T_ + s * SEGL_)) * E_ + e;
    const float4* mod4 = reinterpret_cast<const float4*>(mod);
    size_t mbase = (size_t)b * T_ + s * SEGL_;
    float h0 = 0.f, h1 = 0.f, h2 = 0.f, h3 = 0.f;
    for (int t = 0; t < SEGL_; t += 4) {
        float g[4]; float4 mm[4];
#pragma unroll
        for (int i = 0; i < 4; i++) {
            g[i]  = __ldg(&gated[base + (size_t)(t + i) * E_]);
            mm[i] = __ldg(&mod4[mbase + t + i]);
        }
#pragma unroll
        for (int i = 0; i < 4; i++) {
            h0 = fmaf(al[0], h0, g[i] * mm[i].x);
            h1 = fmaf(al[1], h1, g[i] * mm[i].y);
            h2 = fmaf(al[2], h2, g[i] * mm[i].z);
            h3 = fmaf(al[3], h3, g[i] * mm[i].w);
        }
    }
    size_t o = (size_t)(b * SEG_ + s) * E_ + e;
    seg4[0 * (B_*SEG_*E_) + o] = h0;
    seg4[1 * (B_*SEG_*E_) + o] = h1;
    seg4[2 * (B_*SEG_*E_) + o] = h2;
    seg4[3 * (B_*SEG_*E_) + o] = h3;
}

__global__ void ema_tr_p2(const float* __restrict__ tau_raws,
                          float* __restrict__ seg4, int b0) {
    int tid = blockIdx.x * blockDim.x + threadIdx.x;
    if (tid >= (B_/2) * E_) return;
    int e = tid & (E_ - 1);
    int b = b0 + (tid >> 10);
#pragma unroll
    for (int d = 0; d < 4; d++) {
        float alpha = 1.0f / (1.0f + expf(tau_raws[d]));
        float aL = 1.0f;
        for (int k = 0; k < SEGL_; k++) aL *= alpha;
        float carry = 0.0f;
        for (int s = 0; s < SEG_; s++) {
            size_t idx = (size_t)d * (B_*SEG_*E_) + (size_t)(b * SEG_ + s) * E_ + e;
            float Es = seg4[idx];
            seg4[idx] = carry;
            carry = fmaf(aL, carry, Es);
        }
    }
}

__global__ void ema_tr_p3(const float* __restrict__ gated,
                          const float* __restrict__ mod,
                          const float* __restrict__ tau_raws,
                          const float* __restrict__ blend,
                          const float* __restrict__ seg4,
                          float* __restrict__ temporal, int b0) {
    int tid = blockIdx.x * blockDim.x + threadIdx.x;
    if (tid >= (B_/2) * E_ * SEG_) return;
    int e = tid & (E_ - 1);
    int s = (tid >> 10) & (SEG_ - 1);
    int b = b0 + (tid >> 15);

    float al[4];
#pragma unroll
    for (int d = 0; d < 4; d++) al[d] = 1.0f / (1.0f + expf(tau_raws[d]));

    float bl[4];
#pragma unroll
    for (int d = 0; d < 4; d++) bl[d] = blend[d * E_ + e];
    float mx = fmaxf(fmaxf(bl[0], bl[1]), fmaxf(bl[2], bl[3]));
    float bw[4], sum = 0.0f;
#pragma unroll
    for (int d = 0; d < 4; d++) { bw[d] = expf(bl[d] - mx); sum += bw[d]; }
    float inv = 1.0f / sum;
#pragma unroll
    for (int d = 0; d < 4; d++) bw[d] *= inv;

    size_t base = ((size_t)(b * T_ + s * SEGL_)) * E_ + e;
    const float4* mod4 = reinterpret_cast<const float4*>(mod);
    size_t mbase = (size_t)b * T_ + s * SEGL_;
    size_t o = (size_t)(b * SEG_ + s) * E_ + e;
    float h0 = seg4[0 * (B_*SEG_*E_) + o];
    float h1 = seg4[1 * (B_*SEG_*E_) + o];
    float h2 = seg4[2 * (B_*SEG_*E_) + o];
    float h3 = seg4[3 * (B_*SEG_*E_) + o];

    for (int t = 0; t < SEGL_; t += 4) {
        float g[4]; float4 mm[4];
#pragma unroll
        for (int i = 0; i < 4; i++) {
            g[i]  = __ldg(&gated[base + (size_t)(t + i) * E_]);
            mm[i] = __ldg(&mod4[mbase + t + i]);
        }
#pragma unroll
        for (int i = 0; i < 4; i++) {
            h0 = fmaf(al[0], h0, g[i] * mm[i].x);
            h1 = fmaf(al[1], h1, g[i] * mm[i].y);
            h2 = fmaf(al[2], h2, g[i] * mm[i].z);
            h3 = fmaf(al[3], h3, g[i] * mm[i].w);
            temporal[base + (size_t)(t + i) * E_] =
                tf32f(bw[0] * h0 + bw[1] * h1 + bw[2] * h2 + bw[3] * h3);
        }
    }
}

// ============================================================================
// tf32 mma.sync GEMM (R10 shape — unchanged; at tf32 HW ceiling ~51% tensor)
// mode: 0 none, 1 sigmoid(.)*extra, 2 gelu, 3 sigmoid, 5 tf32f(sigmoid(.)*extra)
// ============================================================================
static constexpr int STAGE_BYTES = 32768;
static constexpr int NSTAGE = 3;
static constexpr int LDC = 132;
static constexpr int DYN_SMEM = NSTAGE * STAGE_BYTES;  // 98304

__global__ void __launch_bounds__(256, 2)
gemm_mma(const float* __restrict__ A, const float* __restrict__ A2, int KA,
         const float* __restrict__ W, const float* __restrict__ bias,
         const float* __restrict__ extra, float* __restrict__ C,
         int N, int K, int mode) {
    extern __shared__ float smem[];
    uint32_t sb = smem_u32(smem);
    int tid = threadIdx.x, wid = tid >> 5, lane = tid & 31;
    int bm = blockIdx.y * 128, bn = blockIdx.x * 128;
    int wm = wid & 1;
    int wn = wid >> 1;

    float acc[4][4][4];
#pragma unroll
    for (int i = 0; i < 4; i++)
#pragma unroll
        for (int j = 0; j < 4; j++)
#pragma unroll
            for (int r = 0; r < 4; r++) acc[i][j][r] = 0.0f;

    const int NC = K / 32;

    int p7 = lane & 7;
    uint32_t aRow[4], bRow[2];
#pragma unroll
    for (int i = 0; i < 4; i++)
        aRow[i] = (uint32_t)(wm * 64 + i * 16 + p7 + 8 * ((lane >> 3) & 1)) * 128u;
#pragma unroll
    for (int j2 = 0; j2 < 2; j2++)
        bRow[j2] = (uint32_t)(wn * 32 + j2 * 16 + p7 + 8 * (lane >> 4)) * 128u;
    uint32_t swzA[4], swzB[4];
#pragma unroll
    for (int ks = 0; ks < 4; ks++) {
        swzA[ks] = (uint32_t)(((ks * 2 + (lane >> 4)) ^ p7) * 16);
        swzB[ks] = (uint32_t)(((ks * 2 + ((lane >> 3) & 1)) ^ p7) * 16);
    }

    auto load_chunk = [&](int c, int s) {
        int k0 = c * 32;
        const float* srcA = A; int ka = k0;
        if (A2 != nullptr && k0 >= KA) { srcA = A2; ka = k0 - KA; }
        uint32_t dstA = sb + (uint32_t)s * STAGE_BYTES;
        uint32_t dstB = dstA + 16384;
#pragma unroll
        for (int q = 0; q < 4; q++) {
            int idx = tid + q * 256;
            int row = idx >> 3, ch = idx & 7;
            uint32_t off = (uint32_t)row * 128u + (uint32_t)((ch ^ (row & 7)) * 16);
            const float* sA = srcA + (size_t)(bm + row) * KA + ka + ch * 4;
            CP_ASYNC16(dstA + off, sA);
            const float* sB = W + (size_t)(bn + row) * K + k0 + ch * 4;
            CP_ASYNC16(dstB + off, sB);
        }
        asm volatile("cp.async.commit_group;" ::: "memory");
    };

    load_chunk(0, 0);
    load_chunk(1, 1);

    for (int c = 0; c < NC; c++) {
        int s = c % NSTAGE;
        if (c < NC - 1) asm volatile("cp.async.wait_group 1;" ::: "memory");
        else            asm volatile("cp.async.wait_group 0;" ::: "memory");
        __syncthreads();
        if (c + 2 < NC) load_chunk(c + 2, (c + 2) % NSTAGE);

        uint32_t baseA = sb + (uint32_t)s * STAGE_BYTES;
        uint32_t baseB = baseA + 16384;
#pragma unroll
        for (int ks = 0; ks < 4; ks++) {
            uint32_t a[4][4], b[2][4];
#pragma unroll
            for (int i = 0; i < 4; i++) LDSM_X4(a[i], baseA + aRow[i] + swzA[ks]);
#pragma unroll
            for (int j2 = 0; j2 < 2; j2++) LDSM_X4(b[j2], baseB + bRow[j2] + swzB[ks]);
#pragma unroll
            for (int i = 0; i < 4; i++)
#pragma unroll
                for (int j = 0; j < 4; j++) {
                    asm volatile(
                        "mma.sync.aligned.m16n8k8.row.col.f32.tf32.tf32.f32 "
                        "{%0,%1,%2,%3}, {%4,%5,%6,%7}, {%8,%9}, {%0,%1,%2,%3};"
                        : "+f"(acc[i][j][0]), "+f"(acc[i][j][1]),
                          "+f"(acc[i][j][2]), "+f"(acc[i][j][3])
                        : "r"(a[i][0]), "r"(a[i][1]), "r"(a[i][2]), "r"(a[i][3]),
                          "r"(b[j >> 1][(j & 1) * 2]), "r"(b[j >> 1][(j & 1) * 2 + 1]));
                }
        }
    }
    __syncthreads();

    float* Cs = smem;
#pragma unroll
    for (int i = 0; i < 4; i++)
#pragma unroll
        for (int j = 0; j < 4; j++) {
            int r0 = wm * 64 + i * 16 + (lane >> 2);
            int c0 = wn * 32 + j * 8 + (lane & 3) * 2;
            *reinterpret_cast<float2*>(Cs + r0 * LDC + c0) =
                make_float2(acc[i][j][0], acc[i][j][1]);
            *reinterpret_cast<float2*>(Cs + (r0 + 8) * LDC + c0) =
                make_float2(acc[i][j][2], acc[i][j][3]);
        }
    __syncthreads();

    for (int t = tid; t < 128 * 32; t += 256) {
        int r = t >> 5, c0 = (t & 31) * 4;
        const float* rg = Cs + r * LDC + c0;
        int m = bm + r, n = bn + c0;
        size_t oidx = (size_t)m * N + n;
        float v[4];
#pragma unroll
        for (int i = 0; i < 4; i++) {
            v[i] = rg[i];
            if (bias != nullptr) v[i] += __ldg(&bias[n + i]);
        }
        if (mode == 1 || mode == 5) {
            float4 ex = *reinterpret_cast<const float4*>(extra + oidx);
            float exv[4] = {ex.x, ex.y, ex.z, ex.w};
#pragma unroll
            for (int i = 0; i < 4; i++) {
                float p = sigmoidf_(v[i]) * exv[i];
                v[i] = (mode == 1) ? p : tf32f(p);
            }
        } else if (mode == 2) {
#pragma unroll
            for (int i = 0; i < 4; i++) v[i] = geluf_(v[i]);
        } else if (mode == 3) {
#pragma unroll
            for (int i = 0; i < 4; i++) v[i] = sigmoidf_(v[i]);
        }
        *reinterpret_cast<float4*>(C + oidx) = make_float4(v[0], v[1], v[2], v[3]);
    }
}

// ---------------- mod = 0.5 + sigmoid(h1 @ Wn2^T + bn2) ---------------------
__global__ void mod_kernel(const float* __restrict__ h1,
                           const float* __restrict__ Wn2,
                           const float* __restrict__ bn2,
                           float* __restrict__ mod) {
    int warp = (blockIdx.x * blockDim.x + threadIdx.x) >> 5;
    int lane = threadIdx.x & 31;
    if (warp >= BT_) return;
    const float* hr = h1 + (size_t)warp * 256;
    float a0 = 0.f, a1 = 0.f, a2 = 0.f, a3 = 0.f;
    for (int k = lane; k < 256; k += 32) {
        float hv = __ldg(&hr[k]);
        a0 = fmaf(hv, __ldg(&Wn2[k]),       a0);
        a1 = fmaf(hv, __ldg(&Wn2[256 + k]), a1);
        a2 = fmaf(hv, __ldg(&Wn2[512 + k]), a2);
        a3 = fmaf(hv, __ldg(&Wn2[768 + k]), a3);
    }
#pragma unroll
    for (int o = 16; o > 0; o >>= 1) {
        a0 += __shfl_xor_sync(0xffffffff, a0, o);
        a1 += __shfl_xor_sync(0xffffffff, a1, o);
        a2 += __shfl_xor_sync(0xffffffff, a2, o);
        a3 += __shfl_xor_sync(0xffffffff, a3, o);
    }
    if (lane == 0) {
        mod[(size_t)warp * 4 + 0] = 0.5f + sigmoidf_(a0 + bn2[0]);
        mod[(size_t)warp * 4 + 1] = 0.5f + sigmoidf_(a1 + bn2[1]);
        mod[(size_t)warp * 4 + 2] = 0.5f + sigmoidf_(a2 + bn2[2]);
        mod[(size_t)warp * 4 + 3] = 0.5f + sigmoidf_(a3 + bn2[3]);
    }
}

// ---------------- in-place LayerNorm over E per row --------------------------
__global__ void ln_kernel(float* __restrict__ out,
                          const float* __restrict__ gamma,
                          const float* __restrict__ beta) {
    int row = blockIdx.x;
    float* p = out + (size_t)row * E_;
    int tid = threadIdx.x;
    float v[4];
    float s = 0.f, ss = 0.f;
#pragma unroll
    for (int i = 0; i < 4; i++) {
        v[i] = p[tid + i * 256];
        s += v[i];
        ss += v[i] * v[i];
    }
#pragma unroll
    for (int o = 16; o > 0; o >>= 1) {
        s  += __shfl_down_sync(0xffffffff, s,  o);
        ss += __shfl_down_sync(0xffffffff, ss, o);
    }
    __shared__ float shs[8], shss[8];
    __shared__ float mu_s, inv_s;
    int wid = tid >> 5, lane = tid & 31;
    if (lane == 0) { shs[wid] = s; shss[wid] = ss; }
    __syncthreads();
    if (tid == 0) {
        float S = 0.f, SS = 0.f;
#pragma unroll
        for (int w = 0; w < 8; w++) { S += shs[w]; SS += shss[w]; }
        float mu  = S / (float)E_;
        float var = SS / (float)E_ - mu * mu;
        mu_s = mu;
        inv_s = rsqrtf(var + 1e-5f);
    }
    __syncthreads();
    float mu = mu_s, iv = inv_s;
#pragma unroll
    for (int i = 0; i < 4; i++) {
        int c = tid + i * 256;
        p[c] = (v[i] - mu) * iv * __ldg(&gamma[c]) + __ldg(&beta[c]);
    }
}

// ---------------- launch -----------------------------------------------------
extern "C" void kernel_launch(void* const* d_in, const int* in_sizes, int n_in,
                              void* d_out, int out_size) {
    const float* x        = (const float*)d_in[0];
    const float* tau_ctx  = (const float*)d_in[1];
    const float* tau_raws = (const float*)d_in[2];
    const float* Wg       = (const float*)d_in[3];
    const float* bg       = (const float*)d_in[4];
    const float* Wn1      = (const float*)d_in[5];
    const float* bn1      = (const float*)d_in[6];
    const float* Wn2      = (const float*)d_in[7];
    const float* bn2      = (const float*)d_in[8];
    const float* blend    = (const float*)d_in[9];
    const float* Wsoma    = (const float*)d_in[10];
    const float* bsoma    = (const float*)d_in[11];
    const float* Wtemp    = (const float*)d_in[12];
    const float* btemp    = (const float*)d_in[13];
    const float* Wout     = (const float*)d_in[14];
    const float* gamma    = (const float*)d_in[15];
    const float* beta     = (const float*)d_in[16];
    float* out = (float*)d_out;

    float *ctx, *gated, *temporal, *gate, *sg, *h1, *mod, *seg, *seg4;
    float *xr, *wgr, *wn1r, *wtr, *wsr, *wor;
    cudaGetSymbolAddress((void**)&ctx,      g_ctx);
    cudaGetSymbolAddress((void**)&gated,    g_gated);
    cudaGetSymbolAddress((void**)&temporal, g_temporal);
    cudaGetSymbolAddress((void**)&gate,     g_gate);
    cudaGetSymbolAddress((void**)&sg,       g_sg);
    cudaGetSymbolAddress((void**)&h1,       g_h1);
    cudaGetSymbolAddress((void**)&mod,      g_mod);
    cudaGetSymbolAddress((void**)&seg,      g_seg);
    cudaGetSymbolAddress((void**)&seg4,     g_seg4);
    cudaGetSymbolAddress((void**)&xr,       g_xr);
    cudaGetSymbolAddress((void**)&wgr,      g_wgr);
    cudaGetSymbolAddress((void**)&wn1r,     g_wn1r);
    cudaGetSymbolAddress((void**)&wtr,      g_wtr);
    cudaGetSymbolAddress((void**)&wsr,      g_wsr);
    cudaGetSymbolAddress((void**)&wor,      g_wor);

    cudaFuncSetAttribute(gemm_mma, cudaFuncAttributeMaxDynamicSharedMemorySize, DYN_SMEM);
    cudaFuncSetAttribute(gemm_mma, cudaFuncAttributePreferredSharedMemoryCarveout,
                         cudaSharedmemCarveoutMaxShared);

    static cudaStream_t s1 = nullptr;
    static cudaEvent_t evA = nullptr, evB = nullptr, evS = nullptr,
                       evG = nullptr, evC = nullptr;
    if (s1 == nullptr) {
        cudaStreamCreateWithFlags(&s1, cudaStreamNonBlocking);
        cudaEventCreateWithFlags(&evA, cudaEventDisableTiming);
        cudaEventCreateWithFlags(&evB, cudaEventDisableTiming);
        cudaEventCreateWithFlags(&evS, cudaEventDisableTiming);
        cudaEventCreateWithFlags(&evG, cudaEventDisableTiming);
        cudaEventCreateWithFlags(&evC, cudaEventDisableTiming);
    }

    const int NSEG_T = B_ * E_ * SEG_;      // 131072
    const int NSEG_H = NSEG_T / 2;          // 65536
    const size_t HOFF = (size_t)(BT_ / 2) * E_;
    dim3 gridE(E_ / 128, BT_ / 128);        // full M
    dim3 gridEH(E_ / 128, BT_ / 256);       // half M
    dim3 gridH(256 / 128, BT_ / 128);

    // ---- s1 t=0: weight rounding (no deps) ----
    round_w2<<<512, 256, 0, s1>>>(Wn1, Wsoma, wn1r, wsr);

    // ---- s0: produce xr + ctx segment sums ----
    ema_ctx_p1_roundx<<<NSEG_T / 256, 256>>>(x, tau_ctx, seg, xr);
    cudaEventRecord(evA, 0);

    // ---- s1: h1 GEMM -> mod (evB early), then soma (evS) ----
    cudaStreamWaitEvent(s1, evA, 0);
    gemm_mma<<<gridH, 256, DYN_SMEM, s1>>>(xr, nullptr, E_, wn1r, bn1, nullptr,
                                           h1, 256, E_, 2);
    mod_kernel<<<(BT_ * 32) / 256, 256, 0, s1>>>(h1, Wn2, bn2, mod);
    cudaEventRecord(evB, s1);
    gemm_mma<<<gridE, 256, DYN_SMEM, s1>>>(xr, nullptr, E_, wsr, bsoma, nullptr,
                                           sg, E_, E_, 2);          // soma_raw
    cudaEventRecord(evS, s1);

    // ---- s0: ctx chain + Wg GEMM ----
    ema_ctx_p2_roundw<<<1024, 256>>>(tau_ctx, seg, Wg, Wtemp, Wout, wgr, wtr, wor);
    ema_ctx_p3<<<NSEG_T / 256, 256>>>(x, tau_ctx, seg, ctx);
    gemm_mma<<<gridE, 256, DYN_SMEM>>>(xr, ctx, E_, wgr, bg, x, gated, E_, 2 * E_, 1);
    cudaEventRecord(evG, 0);

    // ================= batch-split pipelined tail =================
    cudaStreamWaitEvent(0, evB, 0);          // s0 needs mod
    cudaStreamWaitEvent(s1, evG, 0);         // s1 needs gated/wtr/wor

    // ---- s0 half 0 ----
    ema_tr_p1<<<NSEG_H / 256, 256>>>(gated, mod, tau_raws, seg4, 0);
    ema_tr_p2<<<(B_/2 * E_) / 256, 256>>>(tau_raws, seg4, 0);
    ema_tr_p3<<<NSEG_H / 256, 256>>>(gated, mod, tau_raws, blend, seg4, temporal, 0);
    cudaStreamWaitEvent(0, evS, 0);          // gate needs sg
    gemm_mma<<<gridEH, 256, DYN_SMEM>>>(temporal, nullptr, E_, wtr, btemp, sg,
                                        gate, E_, E_, 5);
    gemm_mma<<<gridEH, 256, DYN_SMEM>>>(gate, nullptr, E_, wor, nullptr, nullptr,
                                        out, E_, E_, 0);
    ln_kernel<<<BT_ / 2, 256>>>(out, gamma, beta);

    // ---- s1 half 1 (sg in-order on s1) ----
    ema_tr_p1<<<NSEG_H / 256, 256, 0, s1>>>(gated, mod, tau_raws, seg4, 2);
    ema_tr_p2<<<(B_/2 * E_) / 256, 256, 0, s1>>>(tau_raws, seg4, 2);
    ema_tr_p3<<<NSEG_H / 256, 256, 0, s1>>>(gated, mod, tau_raws, blend, seg4,
                                            temporal, 2);
    gemm_mma<<<gridEH, 256, DYN_SMEM, s1>>>(temporal + HOFF, nullptr, E_, wtr, btemp,
                                            sg + HOFF, gate + HOFF, E_, E_, 5);
    gemm_mma<<<gridEH, 256, DYN_SMEM, s1>>>(gate + HOFF, nullptr, E_, wor, nullptr,
                                            nullptr, out + HOFF, E_, E_, 0);
    ln_kernel<<<BT_ / 2, 256, 0, s1>>>(out + HOFF, gamma, beta);
    cudaEventRecord(evC, s1);

    // ---- final join ----
    cudaStreamWaitEvent(0, evC, 0);
}